// round 9
// baseline (speedup 1.0000x reference)
#include <cuda_runtime.h>
#include <cstdint>

// ---------------- problem constants ----------------
#define Nn   2048
#define Bb   16
#define Cc   64
#define Tt   12
#define Ee   10
#define Oo   64
#define MC   (Bb*Cc*Tt)        // 12288
#define NT   (Nn*Tt)           // 24576
#define ONT  (Oo*Nn*Tt)        // 1572864
#define XAV_SIZE (Bb*ONT)      // 25165824 floats

// ---------------- scratch (device globals) ----------------
__device__ float g_A [Nn*Nn];
__device__ float g_PT[Nn*Nn];
__device__ float g_Xr[(size_t)Nn*MC];   // [node][12288], tf32-rounded
__device__ float g_G1[(size_t)Nn*MC];
__device__ float g_G2[(size_t)Nn*MC];
__device__ float g_D1[(size_t)Nn*MC];
__device__ float g_D2[(size_t)Nn*MC];

// ---------------- helpers ----------------
__device__ __forceinline__ uint32_t smem_u32(const void* p){
    uint32_t a;
    asm("{ .reg .u64 t; cvta.to.shared.u64 t, %1; cvt.u32.u64 %0, t; }" : "=r"(a) : "l"(p));
    return a;
}
__device__ __forceinline__ float rtf32(float f){
    uint32_t u; asm("cvt.rna.tf32.f32 %0, %1;" : "=r"(u) : "f"(f));
    return __uint_as_float(u);
}
__device__ __forceinline__ unsigned long long pack_dup(float a){
    unsigned long long r; asm("mov.b64 %0, {%1, %1};" : "=l"(r) : "f"(a)); return r;
}
__device__ __forceinline__ void fma2(unsigned long long &acc,
                                     unsigned long long a, unsigned long long b){
    asm("fma.rn.f32x2 %0, %1, %2, %0;" : "+l"(acc) : "l"(a), "l"(b));
}
__device__ __forceinline__ void mma_tf32(float* d,
    uint32_t a0, uint32_t a1, uint32_t a2, uint32_t a3,
    uint32_t b0, uint32_t b1)
{
    asm volatile(
        "mma.sync.aligned.m16n8k8.row.col.f32.tf32.tf32.f32 "
        "{%0,%1,%2,%3}, {%4,%5,%6,%7}, {%8,%9}, {%0,%1,%2,%3};"
        : "+f"(d[0]), "+f"(d[1]), "+f"(d[2]), "+f"(d[3])
        : "r"(a0), "r"(a1), "r"(a2), "r"(a3), "r"(b0), "r"(b1));
}
__device__ __forceinline__ void cp16(uint32_t d, const float* s){
    asm volatile("cp.async.cg.shared.global [%0], [%1], 16;" :: "r"(d), "l"(s));
}
#define CP_COMMIT() asm volatile("cp.async.commit_group;" ::: "memory")
#define CP_WAIT2()  asm volatile("cp.async.wait_group 2;" ::: "memory")

// ---------------- A = rowsoftmax(relu(E E^T)) , tf32-rounded ----------------
__global__ __launch_bounds__(256) void compute_A_kernel(const float* __restrict__ emb)
{
    __shared__ float row[Nn];
    __shared__ float red[256];
    const int n = blockIdx.x, tid = threadIdx.x;
    float e[Ee];
#pragma unroll
    for (int d = 0; d < Ee; d++) e[d] = emb[n*Ee + d];
    float lmax = -1e30f;
    for (int m = tid; m < Nn; m += 256){
        float s = 0.f;
#pragma unroll
        for (int d = 0; d < Ee; d++) s += e[d] * emb[m*Ee + d];
        s = fmaxf(s, 0.f);
        row[m] = s; lmax = fmaxf(lmax, s);
    }
    red[tid] = lmax; __syncthreads();
    for (int s = 128; s > 0; s >>= 1){ if (tid < s) red[tid] = fmaxf(red[tid], red[tid+s]); __syncthreads(); }
    const float mx = red[0]; __syncthreads();
    float lsum = 0.f;
    for (int m = tid; m < Nn; m += 256){ float v = expf(row[m] - mx); row[m] = v; lsum += v; }
    red[tid] = lsum; __syncthreads();
    for (int s = 128; s > 0; s >>= 1){ if (tid < s) red[tid] += red[tid+s]; __syncthreads(); }
    const float inv = 1.f / red[0];
    for (int m = tid; m < Nn; m += 256)
        g_A[(size_t)n*Nn + m] = rtf32(row[m] * inv);
}

// ---------------- x[B,C,N,T] -> Xr[N][bc*12+t] (tf32-rounded) ----------------
__global__ __launch_bounds__(256) void transpose_X_kernel(const float* __restrict__ x)
{
    int g  = blockIdx.x * 256 + threadIdx.x;
    int n  = g >> 10;
    int bc = g & 1023;
    const float4* src = (const float4*)(x + ((size_t)bc*Nn + n) * Tt);
    float4*       dst = (float4*)(g_Xr + (size_t)n*MC + (size_t)bc*Tt);
#pragma unroll
    for (int i = 0; i < 3; i++){
        float4 v = src[i];
        dst[i] = make_float4(rtf32(v.x), rtf32(v.y), rtf32(v.z), rtf32(v.w));
    }
}

// ---------------- PT[w][v] = support[v][w] (tf32-rounded) ----------------
__global__ void transpose2k_kernel(const float* __restrict__ S, float* __restrict__ D)
{
    __shared__ float tile[32][33];
    const int x0 = blockIdx.x*32, y0 = blockIdx.y*32;
    const int tx = threadIdx.x, ty = threadIdx.y;     // (32,8)
#pragma unroll
    for (int j = 0; j < 4; j++)
        tile[ty + j*8][tx] = S[(size_t)(y0 + ty + j*8)*Nn + x0 + tx];
    __syncthreads();
#pragma unroll
    for (int j = 0; j < 4; j++)
        D[(size_t)(x0 + ty + j*8)*Nn + y0 + tx] = rtf32(tile[tx][ty + j*8]);
}

// ---------------- tf32 mma.sync GEMM, 4-stage cp.async, warp tile 64x64 ----------------
// C[m][n] = alpha * sum_k A[m][k]*B[k][n] + beta*Res[m][n]
// CTA tile 128x128, BK=16, 4 warps in 2(m) x 2(n), warp tile 64x64 via m16n8k8.
#define SA 20                       // A smem row stride (words)
#define SB 136                      // B smem row stride (words)
#define A_STAGE_W (128*SA)          // 2560 words
#define B_STAGE_W (16*SB)           // 2176 words
#define STAGE_W   (A_STAGE_W + B_STAGE_W)
#define STAGE_BYTES (STAGE_W*4)     // 18944
#define GEMM_SMEM (4*STAGE_BYTES)   // 75776

__global__ __launch_bounds__(128, 2) void mma_gemm(
    int Ncols, float alpha,
    const float* __restrict__ A,
    const float* __restrict__ B,
    float* __restrict__ C,
    const float* __restrict__ Res, float beta, int roundOut)
{
    extern __shared__ __align__(16) uint32_t smw[];
    const uint32_t sbase = smem_u32(smw);

    const int tid  = threadIdx.x;
    const int lane = tid & 31;
    const int wid  = tid >> 5;          // 0..3
    const int wm   = wid >> 1;          // 0..1 -> 64 rows
    const int wn   = wid & 1;           // 0..1 -> 64 cols
    const int gy   = lane >> 2;         // 0..7
    const int gx   = lane & 3;          // 0..3

    const int nBase = blockIdx.x * 128;
    const int mBase = blockIdx.y * 128;

    // cp.async mapping (128 threads, 8 x 16B each per stage)
    const int aRow = tid;                    // 0..127, full k-row of 16
    const int bKr  = tid >> 3;               // 0..15
    const int bN0  = (tid & 7) * 16;         // 0..112
    const float* aSrc = A + (size_t)(mBase + aRow)*2048;
    const float* bSrc = B + (size_t)bKr*Ncols + nBase + bN0;
    const uint32_t aDst = (uint32_t)(aRow*SA) * 4;
    const uint32_t bDst = (uint32_t)(A_STAGE_W + bKr*SB + bN0) * 4;

#define ISSUE_STAGE(kt_) do { \
        uint32_t sb_ = sbase + ((kt_) & 3) * STAGE_BYTES; \
        const float* as_ = aSrc + (kt_)*16; \
        const float* bs_ = bSrc + (size_t)(kt_)*16*Ncols; \
        cp16(sb_ + aDst,      as_); \
        cp16(sb_ + aDst + 16, as_ + 4); \
        cp16(sb_ + aDst + 32, as_ + 8); \
        cp16(sb_ + aDst + 48, as_ + 12); \
        cp16(sb_ + bDst,      bs_); \
        cp16(sb_ + bDst + 16, bs_ + 4); \
        cp16(sb_ + bDst + 32, bs_ + 8); \
        cp16(sb_ + bDst + 48, bs_ + 12); \
    } while(0)

    ISSUE_STAGE(0); CP_COMMIT();
    ISSUE_STAGE(1); CP_COMMIT();
    ISSUE_STAGE(2); CP_COMMIT();

    float acc[4][8][4];
#pragma unroll
    for (int mt = 0; mt < 4; mt++)
#pragma unroll
        for (int nt = 0; nt < 8; nt++)
#pragma unroll
            for (int r = 0; r < 4; r++) acc[mt][nt][r] = 0.f;

    const int NKT = 2048 / 16;   // 128
    for (int kt = 0; kt < NKT; kt++){
        CP_WAIT2();
        __syncthreads();
        const int pf = kt + 3;
        if (pf < NKT) ISSUE_STAGE(pf);
        CP_COMMIT();

        const uint32_t* Ap = smw + (kt & 3) * STAGE_W;
        const uint32_t* Bp = Ap + A_STAGE_W;
#pragma unroll
        for (int ks = 0; ks < 2; ks++){
            const int k = ks * 8;
            uint32_t a[4][4];
#pragma unroll
            for (int mt = 0; mt < 4; mt++){
                const int rbase = wm*64 + mt*16;
                a[mt][0] = Ap[(rbase + gy    )*SA + k + gx    ];
                a[mt][1] = Ap[(rbase + gy + 8)*SA + k + gx    ];
                a[mt][2] = Ap[(rbase + gy    )*SA + k + gx + 4];
                a[mt][3] = Ap[(rbase + gy + 8)*SA + k + gx + 4];
            }
#pragma unroll
            for (int nt = 0; nt < 8; nt++){
                const int nb = wn*64 + nt*8 + gy;
                uint32_t b0 = Bp[(k + gx    )*SB + nb];
                uint32_t b1 = Bp[(k + gx + 4)*SB + nb];
#pragma unroll
                for (int mt = 0; mt < 4; mt++)
                    mma_tf32(acc[mt][nt], a[mt][0], a[mt][1], a[mt][2], a[mt][3], b0, b1);
            }
        }
    }
#undef ISSUE_STAGE

    // writeout
#pragma unroll
    for (int mt = 0; mt < 4; mt++){
#pragma unroll
        for (int nt = 0; nt < 8; nt++){
            const int row0 = mBase + wm*64 + mt*16 + gy;
            const int col0 = nBase + wn*64 + nt*8 + gx*2;
            float v0 = acc[mt][nt][0] * alpha;
            float v1 = acc[mt][nt][1] * alpha;
            float v2 = acc[mt][nt][2] * alpha;
            float v3 = acc[mt][nt][3] * alpha;
            if (Res){
                float2 r0 = *(const float2*)(Res + (size_t)row0    *Ncols + col0);
                float2 r1 = *(const float2*)(Res + (size_t)(row0+8)*Ncols + col0);
                v0 += beta * r0.x; v1 += beta * r0.y;
                v2 += beta * r1.x; v3 += beta * r1.y;
            }
            if (roundOut){
                v0 = rtf32(v0); v1 = rtf32(v1); v2 = rtf32(v2); v3 = rtf32(v3);
            }
            *(float2*)(C + (size_t)row0    *Ncols + col0) = make_float2(v0, v1);
            *(float2*)(C + (size_t)(row0+8)*Ncols + col0) = make_float2(v2, v3);
        }
    }
}

// ---------------- per-node epilogue ----------------
// sIn padded layout: [k=3][b=16][772 words: c*12+t (768) + 4 pad]
#define PB   772
#define PK   (16*PB)                 // 12352 words per k-section
#define EPI_IN_W   (3*PK)            // 37056
#define EPI_SMEM   ((EPI_IN_W + 12288 + 64) * (int)sizeof(float))  // 197,632 B

__global__ __launch_bounds__(256) void epilogue_kernel(
    const float* __restrict__ emb,
    const float* __restrict__ wsrc,
    const float* __restrict__ bsrc,
    float* __restrict__ out, int mode)
{
    extern __shared__ float sm[];
    float* sIn = sm;                 // EPI_IN_W (padded)
    float* sW  = sm + EPI_IN_W;      // 12288
    float* sB  = sW + 12288;         // 64
    const int n = blockIdx.x, tid = threadIdx.x;

    const float* s0 = g_Xr;
    const float* s1 = (mode == 0) ? g_G1 : g_D1;
    const float* s2 = (mode == 0) ? g_G2 : g_D2;
    const size_t off = (size_t)n * MC;

    // load 3 input rows into padded smem: float4 idx mapping
    for (int idx = tid; idx < 3*16*192; idx += 256){
        const int k   = idx / 3072;
        const int rem = idx - k*3072;
        const int b   = rem / 192;
        const int q   = rem - b*192;
        const float* srcp = (k == 0) ? s0 : (k == 1 ? s1 : s2);
        float4 v = ((const float4*)(srcp + off))[rem];
        ((float4*)sIn)[k*3088 + b*193 + q] = v;
    }
    if (mode == 0){
        float e[Ee];
#pragma unroll
        for (int d = 0; d < Ee; d++) e[d] = emb[n*Ee + d];
        for (int i = tid; i < 12288; i += 256){
            float s = 0.f;
#pragma unroll
            for (int d = 0; d < Ee; d++) s += e[d] * wsrc[d*12288 + i];
            sW[i] = s;
        }
        if (tid < Oo){
            float s = 0.f;
#pragma unroll
            for (int d = 0; d < Ee; d++) s += e[d] * bsrc[d*Oo + tid];
            sB[tid] = s;
        }
    } else {
        for (int i = tid; i < 12288; i += 256) sW[i] = wsrc[i];
        if (tid < Oo) sB[tid] = bsrc[tid];
    }
    __syncthreads();

    // thread (ty,tx): tx = b (0..15), ty -> o group of 4
    const int ty = tid >> 4, tx = tid & 15;
    const int oBase = ty * 4;

    unsigned long long acc[12][2];
#pragma unroll
    for (int t = 0; t < 12; t++){ acc[t][0] = 0ULL; acc[t][1] = 0ULL; }

    for (int kc = 0; kc < 192; kc++){
        const int k = kc >> 6;
        const int c = kc & 63;
        const float4* src = (const float4*)(sIn + k*PK + tx*PB + c*12);
        float4 v0 = src[0], v1 = src[1], v2 = src[2];
        const unsigned long long* wp = (const unsigned long long*)(sW + kc*64 + oBase);
        unsigned long long w01 = wp[0], w23 = wp[1];
        float tv[12] = {v0.x,v0.y,v0.z,v0.w, v1.x,v1.y,v1.z,v1.w, v2.x,v2.y,v2.z,v2.w};
#pragma unroll
        for (int t = 0; t < 12; t++){
            unsigned long long ap = pack_dup(tv[t]);
            fma2(acc[t][0], ap, w01);
            fma2(acc[t][1], ap, w23);
        }
    }

    float* outBase = out + (mode ? (size_t)XAV_SIZE : 0)
                   + (size_t)tx*ONT + (size_t)n*Tt;
#pragma unroll
    for (int j = 0; j < 4; j++){
        const float bia = sB[oBase + j];
        float v[12];
#pragma unroll
        for (int t = 0; t < 12; t++){
            float2 f = *reinterpret_cast<float2*>(&acc[t][j >> 1]);
            v[t] = ((j & 1) ? f.y : f.x) + bia;
        }
        float4* op = (float4*)(outBase + (size_t)(oBase + j)*NT);
        op[0] = make_float4(v[0], v[1], v[2],  v[3]);
        op[1] = make_float4(v[4], v[5], v[6],  v[7]);
        op[2] = make_float4(v[8], v[9], v[10], v[11]);
    }
}

// ---------------- launch ----------------
extern "C" void kernel_launch(void* const* d_in, const int* in_sizes, int n_in,
                              void* d_out, int out_size)
{
    const float* x     = (const float*)d_in[0];
    const float* emb   = (const float*)d_in[1];
    const float* sup   = (const float*)d_in[2];
    const float* wpool = (const float*)d_in[3];
    const float* bpool = (const float*)d_in[4];
    const float* mlp_w = (const float*)d_in[5];
    const float* mlp_b = (const float*)d_in[6];
    float* out = (float*)d_out;

    cudaFuncSetAttribute(epilogue_kernel, cudaFuncAttributeMaxDynamicSharedMemorySize, EPI_SMEM);
    cudaFuncSetAttribute(mma_gemm, cudaFuncAttributeMaxDynamicSharedMemorySize, GEMM_SMEM);

    float *pA, *pPT, *pXr, *pG1, *pG2, *pD1, *pD2;
    cudaGetSymbolAddress((void**)&pA,  g_A);
    cudaGetSymbolAddress((void**)&pPT, g_PT);
    cudaGetSymbolAddress((void**)&pXr, g_Xr);
    cudaGetSymbolAddress((void**)&pG1, g_G1);
    cudaGetSymbolAddress((void**)&pG2, g_G2);
    cudaGetSymbolAddress((void**)&pD1, g_D1);
    cudaGetSymbolAddress((void**)&pD2, g_D2);

    // precompute (all tf32-rounded at the producer)
    compute_A_kernel<<<Nn, 256>>>(emb);
    transpose_X_kernel<<<(Nn*1024)/256, 256>>>(x);
    transpose2k_kernel<<<dim3(Nn/32, Nn/32), dim3(32, 8)>>>(sup, pPT);

    // big GEMMs [2048 x 12288]
    dim3 gBig(MC/128, 16);
    // G1 = A @ Xr (tf32-rounded output: consumed by G2 GEMM)
    mma_gemm<<<gBig, 128, GEMM_SMEM>>>(MC, 1.f, pA, pXr, pG1, nullptr, 0.f, 1);
    // G2 = 2*A @ G1 - Xr   ( == (2A^2 - I) @ X )
    mma_gemm<<<gBig, 128, GEMM_SMEM>>>(MC, 2.f, pA, pG1, pG2, pXr, -1.f, 0);
    // D1 = PT @ Xr (tf32-rounded output: consumed by D2 GEMM)
    mma_gemm<<<gBig, 128, GEMM_SMEM>>>(MC, 1.f, pPT, pXr, pD1, nullptr, 0.f, 1);
    // D2 = PT @ D1
    mma_gemm<<<gBig, 128, GEMM_SMEM>>>(MC, 1.f, pPT, pD1, pD2, nullptr, 0.f, 0);

    // epilogues
    epilogue_kernel<<<Nn, 256, EPI_SMEM>>>(emb, wpool, bpool, out, 0);
    epilogue_kernel<<<Nn, 256, EPI_SMEM>>>(emb, mlp_w, mlp_b, out, 1);
}

// round 10
// speedup vs baseline: 1.7977x; 1.7977x over previous
#include <cuda_runtime.h>
#include <cuda_fp16.h>
#include <cstdint>

// ---------------- problem constants ----------------
#define Nn   2048
#define Bb   16
#define Cc   64
#define Tt   12
#define Ee   10
#define Oo   64
#define MC   (Bb*Cc*Tt)        // 12288
#define NT   (Nn*Tt)           // 24576
#define ONT  (Oo*Nn*Tt)        // 1572864
#define XAV_SIZE (Bb*ONT)      // 25165824 floats

// ---------------- scratch (device globals) ----------------
__device__ __half  g_Ah [(size_t)Nn*Nn];        // softmax adjacency, half, row-major
__device__ __half  g_PTh[(size_t)Nn*Nn];        // support^T, half, row-major
__device__ float    g_Xr [(size_t)Nn*MC];       // fp32, for epilogue + G2 residual
__device__ uint32_t g_hXr[(size_t)(Nn/2)*MC];   // packed half pairs [k/2][n]
__device__ uint32_t g_hG1[(size_t)(Nn/2)*MC];
__device__ uint32_t g_hD1[(size_t)(Nn/2)*MC];
__device__ float    g_G1[(size_t)Nn*MC];
__device__ float    g_G2[(size_t)Nn*MC];
__device__ float    g_D1[(size_t)Nn*MC];
__device__ float    g_D2[(size_t)Nn*MC];

// ---------------- helpers ----------------
__device__ __forceinline__ uint32_t smem_u32(const void* p){
    uint32_t a;
    asm("{ .reg .u64 t; cvta.to.shared.u64 t, %1; cvt.u32.u64 %0, t; }" : "=r"(a) : "l"(p));
    return a;
}
__device__ __forceinline__ unsigned long long pack_dup(float a){
    unsigned long long r; asm("mov.b64 %0, {%1, %1};" : "=l"(r) : "f"(a)); return r;
}
__device__ __forceinline__ void fma2(unsigned long long &acc,
                                     unsigned long long a, unsigned long long b){
    asm("fma.rn.f32x2 %0, %1, %2, %0;" : "+l"(acc) : "l"(a), "l"(b));
}
__device__ __forceinline__ void mma_f16(float* d,
    uint32_t a0, uint32_t a1, uint32_t a2, uint32_t a3,
    uint32_t b0, uint32_t b1)
{
    asm volatile(
        "mma.sync.aligned.m16n8k16.row.col.f32.f16.f16.f32 "
        "{%0,%1,%2,%3}, {%4,%5,%6,%7}, {%8,%9}, {%0,%1,%2,%3};"
        : "+f"(d[0]), "+f"(d[1]), "+f"(d[2]), "+f"(d[3])
        : "r"(a0), "r"(a1), "r"(a2), "r"(a3), "r"(b0), "r"(b1));
}
__device__ __forceinline__ void cp16(uint32_t d, const void* s){
    asm volatile("cp.async.cg.shared.global [%0], [%1], 16;" :: "r"(d), "l"(s));
}
#define CP_COMMIT() asm volatile("cp.async.commit_group;" ::: "memory")
#define CP_WAIT2()  asm volatile("cp.async.wait_group 2;" ::: "memory")

__device__ __forceinline__ uint32_t pack2h(float lo, float hi){
    __half2 h = __floats2half2_rn(lo, hi);
    return *reinterpret_cast<uint32_t*>(&h);
}

// ---------------- A = rowsoftmax(relu(E E^T)) -> half ----------------
__global__ __launch_bounds__(256) void compute_A_kernel(const float* __restrict__ emb)
{
    __shared__ float row[Nn];
    __shared__ float red[256];
    const int n = blockIdx.x, tid = threadIdx.x;
    float e[Ee];
#pragma unroll
    for (int d = 0; d < Ee; d++) e[d] = emb[n*Ee + d];
    float lmax = -1e30f;
    for (int m = tid; m < Nn; m += 256){
        float s = 0.f;
#pragma unroll
        for (int d = 0; d < Ee; d++) s += e[d] * emb[m*Ee + d];
        s = fmaxf(s, 0.f);
        row[m] = s; lmax = fmaxf(lmax, s);
    }
    red[tid] = lmax; __syncthreads();
    for (int s = 128; s > 0; s >>= 1){ if (tid < s) red[tid] = fmaxf(red[tid], red[tid+s]); __syncthreads(); }
    const float mx = red[0]; __syncthreads();
    float lsum = 0.f;
    for (int m = tid; m < Nn; m += 256){ float v = expf(row[m] - mx); row[m] = v; lsum += v; }
    red[tid] = lsum; __syncthreads();
    for (int s = 128; s > 0; s >>= 1){ if (tid < s) red[tid] += red[tid+s]; __syncthreads(); }
    const float inv = 1.f / red[0];
    for (int m = tid; m < Nn; m += 256)
        g_Ah[(size_t)n*Nn + m] = __float2half(row[m] * inv);
}

// ---- x[B,C,N,T] -> Xr fp32 [n][bc*12+t]  +  hXr packed [n/2][bc*12+t] ----
__global__ __launch_bounds__(256) void transpose_X_kernel(const float* __restrict__ x)
{
    int g  = blockIdx.x * 256 + threadIdx.x;   // 0 .. (Nn/2)*1024-1
    int np = g >> 10;
    int bc = g & 1023;
    const int n0 = np*2;
    const float4* s0 = (const float4*)(x + ((size_t)bc*Nn + n0    ) * Tt);
    const float4* s1 = (const float4*)(x + ((size_t)bc*Nn + n0 + 1) * Tt);
    float4 a0 = s0[0], a1 = s0[1], a2 = s0[2];
    float4 b0 = s1[0], b1 = s1[1], b2 = s1[2];
    float4* d0 = (float4*)(g_Xr + (size_t)n0*MC + (size_t)bc*Tt);
    float4* d1 = (float4*)(g_Xr + (size_t)(n0+1)*MC + (size_t)bc*Tt);
    d0[0]=a0; d0[1]=a1; d0[2]=a2;
    d1[0]=b0; d1[1]=b1; d1[2]=b2;
    uint4* hp = (uint4*)(g_hXr + (size_t)np*MC + (size_t)bc*Tt);
    hp[0] = make_uint4(pack2h(a0.x,b0.x), pack2h(a0.y,b0.y), pack2h(a0.z,b0.z), pack2h(a0.w,b0.w));
    hp[1] = make_uint4(pack2h(a1.x,b1.x), pack2h(a1.y,b1.y), pack2h(a1.z,b1.z), pack2h(a1.w,b1.w));
    hp[2] = make_uint4(pack2h(a2.x,b2.x), pack2h(a2.y,b2.y), pack2h(a2.z,b2.z), pack2h(a2.w,b2.w));
}

// ---------------- PTh[w][v] = support[v][w] (half) ----------------
__global__ void transpose2k_kernel(const float* __restrict__ S, __half* __restrict__ D)
{
    __shared__ float tile[32][33];
    const int x0 = blockIdx.x*32, y0 = blockIdx.y*32;
    const int tx = threadIdx.x, ty = threadIdx.y;     // (32,8)
#pragma unroll
    for (int j = 0; j < 4; j++)
        tile[ty + j*8][tx] = S[(size_t)(y0 + ty + j*8)*Nn + x0 + tx];
    __syncthreads();
#pragma unroll
    for (int j = 0; j < 4; j++)
        D[(size_t)(x0 + ty + j*8)*Nn + y0 + tx] = __float2half(tile[tx][ty + j*8]);
}

// ---------------- fp16 mma.sync GEMM, 4-stage cp.async ----------------
// C[m][n] = alpha * sum_k A[m][k]*B[k][n] + beta*Res[m][n] ; optional packed-half out.
// A half row-major [2048 x 2048]; B packed uint32 [1024][Ncols] ({k,k+1} per word).
// CTA 128x128, BK=32, 8 warps 4(m) x 2(n), warp 32x64 via m16n8k16.
#define SAw 20                       // A smem row stride (uint32 words = half-pairs)
#define SBw 136                      // B smem k-pair row stride (words)
#define A_STAGE_W (128*SAw)          // 2560 words
#define B_STAGE_W (16*SBw)           // 2176 words
#define STAGE_W   (A_STAGE_W + B_STAGE_W)
#define STAGE_BYTES (STAGE_W*4)      // 18944
#define GEMM_SMEM (4*STAGE_BYTES)    // 75776

__global__ __launch_bounds__(256, 2) void mma_gemm(
    int Ncols, float alpha,
    const __half* __restrict__ A,
    const uint32_t* __restrict__ B,
    float* __restrict__ C,
    const float* __restrict__ Res, float beta,
    __half* __restrict__ hOut)
{
    extern __shared__ __align__(16) uint32_t smw[];
    const uint32_t sbase = smem_u32(smw);

    const int tid  = threadIdx.x;
    const int lane = tid & 31;
    const int wid  = tid >> 5;
    const int wm   = wid >> 1;          // 0..3
    const int wn   = wid & 1;           // 0..1
    const int gy   = lane >> 2;         // 0..7
    const int gx   = lane & 3;          // 0..3

    const int nBase = blockIdx.x * 128;
    const int mBase = blockIdx.y * 128;

    // cp.async mapping: per stage, A 8192B + B 8192B, 256 thr x 2+2 cp16
    const int aRow = tid >> 1;               // 0..127
    const int aH   = (tid & 1);              // half-row selector (32B each)
    const int bKr  = tid >> 4;               // 0..15 (k-pair row)
    const int bN0  = (tid & 15) * 8;         // word offset 0..120
    const __half* aSrc = A + (size_t)(mBase + aRow)*2048 + aH*16;
    const uint32_t* bSrc = B + (size_t)bKr*Ncols + nBase + bN0;
    const uint32_t aDst = (uint32_t)(aRow*SAw + aH*8) * 4;
    const uint32_t bDst = (uint32_t)(A_STAGE_W + bKr*SBw + bN0) * 4;

#define ISSUE_STAGE(kt_) do { \
        uint32_t sb_ = sbase + ((kt_) & 3) * STAGE_BYTES; \
        const __half* as_ = aSrc + (kt_)*32; \
        const uint32_t* bs_ = bSrc + (size_t)(kt_)*16*Ncols; \
        cp16(sb_ + aDst,      as_); \
        cp16(sb_ + aDst + 16, as_ + 8); \
        cp16(sb_ + bDst,      bs_); \
        cp16(sb_ + bDst + 16, bs_ + 4); \
    } while(0)

    ISSUE_STAGE(0); CP_COMMIT();
    ISSUE_STAGE(1); CP_COMMIT();
    ISSUE_STAGE(2); CP_COMMIT();

    float acc[2][8][4];
#pragma unroll
    for (int mt = 0; mt < 2; mt++)
#pragma unroll
        for (int nt = 0; nt < 8; nt++)
#pragma unroll
            for (int r = 0; r < 4; r++) acc[mt][nt][r] = 0.f;

    const int NKT = 2048 / 32;   // 64 k-tiles
    for (int kt = 0; kt < NKT; kt++){
        CP_WAIT2();
        __syncthreads();
        const int pf = kt + 3;
        if (pf < NKT) ISSUE_STAGE(pf);
        CP_COMMIT();

        const uint32_t* Ap = smw + (kt & 3) * STAGE_W;
        const uint32_t* Bp = Ap + A_STAGE_W;
#pragma unroll
        for (int ks = 0; ks < 2; ks++){
            const int k = ks * 8;               // word offset within rows
            uint32_t a[2][4];
#pragma unroll
            for (int mt = 0; mt < 2; mt++){
                const int rbase = wm*32 + mt*16;
                a[mt][0] = Ap[(rbase + gy    )*SAw + k + gx    ];
                a[mt][1] = Ap[(rbase + gy + 8)*SAw + k + gx    ];
                a[mt][2] = Ap[(rbase + gy    )*SAw + k + gx + 4];
                a[mt][3] = Ap[(rbase + gy + 8)*SAw + k + gx + 4];
            }
#pragma unroll
            for (int nt = 0; nt < 8; nt++){
                const int nb = wn*64 + nt*8 + gy;
                uint32_t b0 = Bp[(k + gx    )*SBw + nb];
                uint32_t b1 = Bp[(k + gx + 4)*SBw + nb];
                mma_f16(acc[0][nt], a[0][0], a[0][1], a[0][2], a[0][3], b0, b1);
                mma_f16(acc[1][nt], a[1][0], a[1][1], a[1][2], a[1][3], b0, b1);
            }
        }
    }
#undef ISSUE_STAGE

    // writeout
#pragma unroll
    for (int mt = 0; mt < 2; mt++){
#pragma unroll
        for (int nt = 0; nt < 8; nt++){
            const int row0 = mBase + wm*32 + mt*16 + gy;
            const int col0 = nBase + wn*64 + nt*8 + gx*2;
            float v0 = acc[mt][nt][0] * alpha;
            float v1 = acc[mt][nt][1] * alpha;
            float v2 = acc[mt][nt][2] * alpha;
            float v3 = acc[mt][nt][3] * alpha;
            if (Res){
                float2 r0 = *(const float2*)(Res + (size_t)row0    *Ncols + col0);
                float2 r1 = *(const float2*)(Res + (size_t)(row0+8)*Ncols + col0);
                v0 += beta * r0.x; v1 += beta * r0.y;
                v2 += beta * r1.x; v3 += beta * r1.y;
            }
            *(float2*)(C + (size_t)row0    *Ncols + col0) = make_float2(v0, v1);
            *(float2*)(C + (size_t)(row0+8)*Ncols + col0) = make_float2(v2, v3);
            if (hOut){
                // packed layout: half index = (row>>1)*2*Ncols + 2*col + (row&1)
                const size_t p0 = (size_t)(row0 >> 1)*2*Ncols + 2*col0 + (row0 & 1);
                const size_t p1 = (size_t)((row0+8) >> 1)*2*Ncols + 2*col0 + ((row0+8) & 1);
                hOut[p0]     = __float2half(v0);
                hOut[p0 + 2] = __float2half(v1);
                hOut[p1]     = __float2half(v2);
                hOut[p1 + 2] = __float2half(v3);
            }
        }
    }
}

// ---------------- per-node epilogue (R7 known-good) ----------------
__global__ __launch_bounds__(256) void epilogue_kernel(
    const float* __restrict__ emb,
    const float* __restrict__ wsrc,
    const float* __restrict__ bsrc,
    float* __restrict__ out, int mode)
{
    extern __shared__ float sm[];
    float* sIn = sm;                 // 3*MC
    float* sW  = sm + 3*MC;          // 12288
    float* sB  = sW + 12288;         // 64
    const int n = blockIdx.x, tid = threadIdx.x;

    const float* s0 = g_Xr;
    const float* s1 = (mode == 0) ? g_G1 : g_D1;
    const float* s2 = (mode == 0) ? g_G2 : g_D2;
    const size_t off = (size_t)n * MC;

    for (int i = tid; i < MC/4; i += 256){
        ((float4*)sIn)[i]          = ((const float4*)(s0 + off))[i];
        ((float4*)(sIn +   MC))[i] = ((const float4*)(s1 + off))[i];
        ((float4*)(sIn + 2*MC))[i] = ((const float4*)(s2 + off))[i];
    }
    if (mode == 0){
        float e[Ee];
#pragma unroll
        for (int d = 0; d < Ee; d++) e[d] = emb[n*Ee + d];
        for (int i = tid; i < 12288; i += 256){
            float s = 0.f;
#pragma unroll
            for (int d = 0; d < Ee; d++) s += e[d] * wsrc[d*12288 + i];
            sW[i] = s;
        }
        if (tid < Oo){
            float s = 0.f;
#pragma unroll
            for (int d = 0; d < Ee; d++) s += e[d] * bsrc[d*Oo + tid];
            sB[tid] = s;
        }
    } else {
        for (int i = tid; i < 12288; i += 256) sW[i] = wsrc[i];
        if (tid < Oo) sB[tid] = bsrc[tid];
    }
    __syncthreads();

    const int ty = tid >> 4, tx = tid & 15;
    const int oBase = ty * 4;
    int offr[12], bArr[12], tArr[12];
#pragma unroll
    for (int i = 0; i < 12; i++){
        int r = tx + 16*i;
        int b = r / 12, t = r - b*12;
        offr[i] = b*(Cc*Tt) + t;
        bArr[i] = b; tArr[i] = t;
    }

    unsigned long long acc[12][2];
#pragma unroll
    for (int i = 0; i < 12; i++){ acc[i][0] = 0ULL; acc[i][1] = 0ULL; }

    for (int kc = 0; kc < 192; kc++){
        const int k = kc >> 6;
        const int c = kc & 63;
        const float* src = sIn + k*MC + c*Tt;
        const unsigned long long* wp = (const unsigned long long*)(sW + kc*64 + oBase);
        unsigned long long w01 = wp[0], w23 = wp[1];
#pragma unroll
        for (int i = 0; i < 12; i++){
            unsigned long long ap = pack_dup(src[offr[i]]);
            fma2(acc[i][0], ap, w01);
            fma2(acc[i][1], ap, w23);
        }
    }

    float* outBase = out + (mode ? (size_t)XAV_SIZE : 0);
#pragma unroll
    for (int i = 0; i < 12; i++){
        const int b = bArr[i], t = tArr[i];
        const size_t p = (size_t)b*ONT + (size_t)n*Tt + t;
        float2 f0 = *reinterpret_cast<float2*>(&acc[i][0]);
        float2 f1 = *reinterpret_cast<float2*>(&acc[i][1]);
        outBase[p + (size_t)(oBase+0)*NT] = f0.x + sB[oBase+0];
        outBase[p + (size_t)(oBase+1)*NT] = f0.y + sB[oBase+1];
        outBase[p + (size_t)(oBase+2)*NT] = f1.x + sB[oBase+2];
        outBase[p + (size_t)(oBase+3)*NT] = f1.y + sB[oBase+3];
    }
}

// ---------------- launch ----------------
#define EPI_SMEM ((3*MC + 12288 + 64) * (int)sizeof(float))

extern "C" void kernel_launch(void* const* d_in, const int* in_sizes, int n_in,
                              void* d_out, int out_size)
{
    const float* x     = (const float*)d_in[0];
    const float* emb   = (const float*)d_in[1];
    const float* sup   = (const float*)d_in[2];
    const float* wpool = (const float*)d_in[3];
    const float* bpool = (const float*)d_in[4];
    const float* mlp_w = (const float*)d_in[5];
    const float* mlp_b = (const float*)d_in[6];
    float* out = (float*)d_out;

    cudaFuncSetAttribute(epilogue_kernel, cudaFuncAttributeMaxDynamicSharedMemorySize, EPI_SMEM);
    cudaFuncSetAttribute(mma_gemm, cudaFuncAttributeMaxDynamicSharedMemorySize, GEMM_SMEM);

    __half *pAh, *pPTh;
    uint32_t *phXr, *phG1, *phD1;
    float *pXr, *pG1, *pG2, *pD1, *pD2;
    cudaGetSymbolAddress((void**)&pAh,  g_Ah);
    cudaGetSymbolAddress((void**)&pPTh, g_PTh);
    cudaGetSymbolAddress((void**)&phXr, g_hXr);
    cudaGetSymbolAddress((void**)&phG1, g_hG1);
    cudaGetSymbolAddress((void**)&phD1, g_hD1);
    cudaGetSymbolAddress((void**)&pXr,  g_Xr);
    cudaGetSymbolAddress((void**)&pG1,  g_G1);
    cudaGetSymbolAddress((void**)&pG2,  g_G2);
    cudaGetSymbolAddress((void**)&pD1,  g_D1);
    cudaGetSymbolAddress((void**)&pD2,  g_D2);

    // precompute
    compute_A_kernel<<<Nn, 256>>>(emb);
    transpose_X_kernel<<<(Nn/2*1024)/256, 256>>>(x);
    transpose2k_kernel<<<dim3(Nn/32, Nn/32), dim3(32, 8)>>>(sup, pPTh);

    // big GEMMs [2048 x 12288]
    dim3 gBig(MC/128, 16);
    // G1 = A @ Xr   (fp32 out for epilogue, packed-half out for G2 chain)
    mma_gemm<<<gBig, 256, GEMM_SMEM>>>(MC, 1.f, pAh, phXr, pG1,
                                       nullptr, 0.f, (__half*)phG1);
    // G2 = 2*A @ G1 - Xr   ( == (2A^2 - I) @ X )
    mma_gemm<<<gBig, 256, GEMM_SMEM>>>(MC, 2.f, pAh, phG1, pG2,
                                       pXr, -1.f, nullptr);
    // D1 = PT @ Xr
    mma_gemm<<<gBig, 256, GEMM_SMEM>>>(MC, 1.f, pPTh, phXr, pD1,
                                       nullptr, 0.f, (__half*)phD1);
    // D2 = PT @ D1
    mma_gemm<<<gBig, 256, GEMM_SMEM>>>(MC, 1.f, pPTh, phD1, pD2,
                                       nullptr, 0.f, nullptr);

    // epilogues
    epilogue_kernel<<<Nn, 256, EPI_SMEM>>>(emb, wpool, bpool, out, 0);
    epilogue_kernel<<<Nn, 256, EPI_SMEM>>>(emb, mlp_w, mlp_b, out, 1);
}

// round 12
// speedup vs baseline: 1.8739x; 1.0424x over previous
#include <cuda_runtime.h>
#include <cuda_fp16.h>
#include <cstdint>

// ---------------- problem constants ----------------
#define Nn   2048
#define Bb   16
#define Cc   64
#define Tt   12
#define Ee   10
#define Oo   64
#define MC   (Bb*Cc*Tt)        // 12288
#define NT   (Nn*Tt)           // 24576
#define ONT  (Oo*Nn*Tt)        // 1572864
#define XAV_SIZE (Bb*ONT)      // 25165824 floats

// ---------------- scratch (device globals) ----------------
__device__ __half  g_Ah [(size_t)Nn*Nn];
__device__ __half  g_PTh[(size_t)Nn*Nn];
__device__ float    g_Xr [(size_t)Nn*MC];
__device__ uint32_t g_hXr[(size_t)(Nn/2)*MC];   // packed half pairs [k/2][n]
__device__ uint32_t g_hG1[(size_t)(Nn/2)*MC];
__device__ uint32_t g_hD1[(size_t)(Nn/2)*MC];
__device__ float    g_G1[(size_t)Nn*MC];
__device__ float    g_G2[(size_t)Nn*MC];
__device__ float    g_D1[(size_t)Nn*MC];
__device__ float    g_D2[(size_t)Nn*MC];

// ---------------- helpers ----------------
__device__ __forceinline__ uint32_t smem_u32(const void* p){
    uint32_t a;
    asm("{ .reg .u64 t; cvta.to.shared.u64 t, %1; cvt.u32.u64 %0, t; }" : "=r"(a) : "l"(p));
    return a;
}
__device__ __forceinline__ unsigned long long pack_dup(float a){
    unsigned long long r; asm("mov.b64 %0, {%1, %1};" : "=l"(r) : "f"(a)); return r;
}
__device__ __forceinline__ void fma2(unsigned long long &acc,
                                     unsigned long long a, unsigned long long b){
    asm("fma.rn.f32x2 %0, %1, %2, %0;" : "+l"(acc) : "l"(a), "l"(b));
}
__device__ __forceinline__ void mma_f16(float* d,
    uint32_t a0, uint32_t a1, uint32_t a2, uint32_t a3,
    uint32_t b0, uint32_t b1)
{
    asm volatile(
        "mma.sync.aligned.m16n8k16.row.col.f32.f16.f16.f32 "
        "{%0,%1,%2,%3}, {%4,%5,%6,%7}, {%8,%9}, {%0,%1,%2,%3};"
        : "+f"(d[0]), "+f"(d[1]), "+f"(d[2]), "+f"(d[3])
        : "r"(a0), "r"(a1), "r"(a2), "r"(a3), "r"(b0), "r"(b1));
}
__device__ __forceinline__ void ldmat4(uint32_t* r, uint32_t addr){
    asm volatile(
        "ldmatrix.sync.aligned.m8n8.x4.shared.b16 {%0,%1,%2,%3}, [%4];"
        : "=r"(r[0]), "=r"(r[1]), "=r"(r[2]), "=r"(r[3]) : "r"(addr));
}
__device__ __forceinline__ void cp16(uint32_t d, const void* s){
    asm volatile("cp.async.cg.shared.global [%0], [%1], 16;" :: "r"(d), "l"(s));
}
__device__ __forceinline__ void cp4(uint32_t d, const void* s){
    asm volatile("cp.async.ca.shared.global [%0], [%1], 4;" :: "r"(d), "l"(s));
}
#define CP_COMMIT() asm volatile("cp.async.commit_group;" ::: "memory")
#define CP_WAIT2()  asm volatile("cp.async.wait_group 2;" ::: "memory")

__device__ __forceinline__ uint32_t pack2h(float lo, float hi){
    __half2 h = __floats2half2_rn(lo, hi);
    return *reinterpret_cast<uint32_t*>(&h);
}

// ---------------- A = rowsoftmax(relu(E E^T)) -> half ----------------
__global__ __launch_bounds__(256) void compute_A_kernel(const float* __restrict__ emb)
{
    __shared__ float row[Nn];
    __shared__ float red[256];
    const int n = blockIdx.x, tid = threadIdx.x;
    float e[Ee];
#pragma unroll
    for (int d = 0; d < Ee; d++) e[d] = emb[n*Ee + d];
    float lmax = -1e30f;
    for (int m = tid; m < Nn; m += 256){
        float s = 0.f;
#pragma unroll
        for (int d = 0; d < Ee; d++) s += e[d] * emb[m*Ee + d];
        s = fmaxf(s, 0.f);
        row[m] = s; lmax = fmaxf(lmax, s);
    }
    red[tid] = lmax; __syncthreads();
    for (int s = 128; s > 0; s >>= 1){ if (tid < s) red[tid] = fmaxf(red[tid], red[tid+s]); __syncthreads(); }
    const float mx = red[0]; __syncthreads();
    float lsum = 0.f;
    for (int m = tid; m < Nn; m += 256){ float v = expf(row[m] - mx); row[m] = v; lsum += v; }
    red[tid] = lsum; __syncthreads();
    for (int s = 128; s > 0; s >>= 1){ if (tid < s) red[tid] += red[tid+s]; __syncthreads(); }
    const float inv = 1.f / red[0];
    for (int m = tid; m < Nn; m += 256)
        g_Ah[(size_t)n*Nn + m] = __float2half(row[m] * inv);
}

// ---- x[B,C,N,T] -> Xr fp32 [n][bc*12+t]  +  hXr packed [n/2][bc*12+t] ----
__global__ __launch_bounds__(256) void transpose_X_kernel(const float* __restrict__ x)
{
    int g  = blockIdx.x * 256 + threadIdx.x;
    int np = g >> 10;
    int bc = g & 1023;
    const int n0 = np*2;
    const float4* s0 = (const float4*)(x + ((size_t)bc*Nn + n0    ) * Tt);
    const float4* s1 = (const float4*)(x + ((size_t)bc*Nn + n0 + 1) * Tt);
    float4 a0 = s0[0], a1 = s0[1], a2 = s0[2];
    float4 b0 = s1[0], b1 = s1[1], b2 = s1[2];
    float4* d0 = (float4*)(g_Xr + (size_t)n0*MC + (size_t)bc*Tt);
    float4* d1 = (float4*)(g_Xr + (size_t)(n0+1)*MC + (size_t)bc*Tt);
    d0[0]=a0; d0[1]=a1; d0[2]=a2;
    d1[0]=b0; d1[1]=b1; d1[2]=b2;
    uint4* hp = (uint4*)(g_hXr + (size_t)np*MC + (size_t)bc*Tt);
    hp[0] = make_uint4(pack2h(a0.x,b0.x), pack2h(a0.y,b0.y), pack2h(a0.z,b0.z), pack2h(a0.w,b0.w));
    hp[1] = make_uint4(pack2h(a1.x,b1.x), pack2h(a1.y,b1.y), pack2h(a1.z,b1.z), pack2h(a1.w,b1.w));
    hp[2] = make_uint4(pack2h(a2.x,b2.x), pack2h(a2.y,b2.y), pack2h(a2.z,b2.z), pack2h(a2.w,b2.w));
}

// ---------------- PTh[w][v] = support[v][w] (half) ----------------
__global__ void transpose2k_kernel(const float* __restrict__ S, __half* __restrict__ D)
{
    __shared__ float tile[32][33];
    const int x0 = blockIdx.x*32, y0 = blockIdx.y*32;
    const int tx = threadIdx.x, ty = threadIdx.y;     // (32,8)
#pragma unroll
    for (int j = 0; j < 4; j++)
        tile[ty + j*8][tx] = S[(size_t)(y0 + ty + j*8)*Nn + x0 + tx];
    __syncthreads();
#pragma unroll
    for (int j = 0; j < 4; j++)
        D[(size_t)(x0 + ty + j*8)*Nn + y0 + tx] = __float2half(tile[tx][ty + j*8]);
}

// ---------------- fp16 mma.sync GEMM, ldmatrix fragments, 4-stage cp.async ----------------
// A half row-major [2048 x 2048], smem [row][20 words].
// B packed uint32 [1024][Ncols] in gmem; smem n-major swizzled [n=128][16 words],
//   word(n,kp) at n*16 + ((kp>>2 ^ ((n>>1)&3))<<2) + (kp&3).
#define SAw 20
#define A_STAGE_BYTES (128*SAw*4)       // 10240
#define B_STAGE_BYTES (128*16*4)        // 8192
#define STAGE_BYTES (A_STAGE_BYTES + B_STAGE_BYTES)  // 18432
#define GEMM_SMEM (4*STAGE_BYTES)       // 73728

__global__ __launch_bounds__(256, 2) void mma_gemm(
    int Ncols, float alpha,
    const __half* __restrict__ A,
    const uint32_t* __restrict__ B,
    float* __restrict__ C,
    const float* __restrict__ Res, float beta,
    __half* __restrict__ hOut)
{
    extern __shared__ __align__(16) uint32_t smw[];
    const uint32_t sbase = smem_u32(smw);

    const int tid  = threadIdx.x;
    const int lane = tid & 31;
    const int wid  = tid >> 5;
    const int wm   = wid >> 1;          // 0..3
    const int wn   = wid & 1;           // 0..1
    const int gy   = lane >> 2;         // 0..7
    const int gx   = lane & 3;          // 0..3
    const int mat  = lane >> 3;         // 0..3 (ldmatrix address group)
    const int mr   = lane & 7;

    const int nBase = blockIdx.x * 128;
    const int mBase = blockIdx.y * 128;

    // ---- fill mappings ----
    const int aRow = tid >> 1;               // 0..127
    const int aH   = (tid & 1);
    const __half* aSrc = A + (size_t)(mBase + aRow)*2048 + aH*16;
    const uint32_t aDst = (uint32_t)(aRow*SAw + aH*8) * 4;

    const int bN  = tid & 127;               // n within tile
    const int bKb = (tid >> 7) * 8;          // kp base (0 or 8)
    const uint32_t* bSrc = B + (size_t)bKb*Ncols + nBase + bN;
    const int zN = (bN >> 1) & 3;
    const uint32_t dstLo = A_STAGE_BYTES + bN*64 + (((bKb>>2)    ) ^ zN)*16;
    const uint32_t dstHi = A_STAGE_BYTES + bN*64 + (((bKb>>2) + 1) ^ zN)*16;

    // ---- ldmatrix address precompute (per lane) ----
    const int aFrow = wm*32 + (mat & 1)*8 + mr;
    const uint32_t aAddr0 = (uint32_t)(aFrow*SAw + (mat >> 1)*4) * 4;
    const uint32_t aAddr1 = aAddr0 + 16*SAw*4;
    uint32_t bAddr[4][2];
#pragma unroll
    for (int q = 0; q < 4; q++){
        const int nq = wn*64 + q*16 + (mat >> 1)*8 + mr;
        const int zq = (nq >> 1) & 3;
#pragma unroll
        for (int ks = 0; ks < 2; ks++){
            const int c = (mat & 1) + 2*ks;
            bAddr[q][ks] = A_STAGE_BYTES + nq*64 + ((c ^ zq) << 4);
        }
    }

#define ISSUE_STAGE(kt_) do { \
        uint32_t sb_ = sbase + ((kt_) & 3) * STAGE_BYTES; \
        const __half* as_ = aSrc + (kt_)*32; \
        cp16(sb_ + aDst,      as_); \
        cp16(sb_ + aDst + 16, as_ + 8); \
        const uint32_t* bs_ = bSrc + (size_t)(kt_)*16*Ncols; \
        _Pragma("unroll") \
        for (int j = 0; j < 8; j++){ \
            uint32_t d_ = (j < 4 ? dstLo : dstHi) + (j & 3)*4; \
            cp4(sb_ + d_, bs_ + (size_t)j*Ncols); \
        } \
    } while(0)

    ISSUE_STAGE(0); CP_COMMIT();
    ISSUE_STAGE(1); CP_COMMIT();
    ISSUE_STAGE(2); CP_COMMIT();

    float acc[2][8][4];
#pragma unroll
    for (int mt = 0; mt < 2; mt++)
#pragma unroll
        for (int nt = 0; nt < 8; nt++)
#pragma unroll
            for (int r = 0; r < 4; r++) acc[mt][nt][r] = 0.f;

    const int NKT = 2048 / 32;   // 64 k-tiles
    for (int kt = 0; kt < NKT; kt++){
        CP_WAIT2();
        __syncthreads();
        const int pf = kt + 3;
        if (pf < NKT) ISSUE_STAGE(pf);
        CP_COMMIT();

        const uint32_t so = sbase + (kt & 3) * STAGE_BYTES;
#pragma unroll
        for (int ks = 0; ks < 2; ks++){
            uint32_t a0[4], a1[4];
            ldmat4(a0, so + aAddr0 + ks*32);
            ldmat4(a1, so + aAddr1 + ks*32);
            uint32_t bb[4][4];
            ldmat4(bb[0], so + bAddr[0][ks]);
            ldmat4(bb[1], so + bAddr[1][ks]);
            ldmat4(bb[2], so + bAddr[2][ks]);
            ldmat4(bb[3], so + bAddr[3][ks]);
#pragma unroll
            for (int nt = 0; nt < 8; nt++){
                const uint32_t b0 = bb[nt >> 1][(nt & 1)*2];
                const uint32_t b1 = bb[nt >> 1][(nt & 1)*2 + 1];
                mma_f16(acc[0][nt], a0[0], a0[1], a0[2], a0[3], b0, b1);
                mma_f16(acc[1][nt], a1[0], a1[1], a1[2], a1[3], b0, b1);
            }
        }
    }
#undef ISSUE_STAGE

    // writeout
#pragma unroll
    for (int mt = 0; mt < 2; mt++){
#pragma unroll
        for (int nt = 0; nt < 8; nt++){
            const int row0 = mBase + wm*32 + mt*16 + gy;
            const int col0 = nBase + wn*64 + nt*8 + gx*2;
            float v0 = acc[mt][nt][0] * alpha;
            float v1 = acc[mt][nt][1] * alpha;
            float v2 = acc[mt][nt][2] * alpha;
            float v3 = acc[mt][nt][3] * alpha;
            if (Res){
                float2 r0 = *(const float2*)(Res + (size_t)row0    *Ncols + col0);
                float2 r1 = *(const float2*)(Res + (size_t)(row0+8)*Ncols + col0);
                v0 += beta * r0.x; v1 += beta * r0.y;
                v2 += beta * r1.x; v3 += beta * r1.y;
            }
            *(float2*)(C + (size_t)row0    *Ncols + col0) = make_float2(v0, v1);
            *(float2*)(C + (size_t)(row0+8)*Ncols + col0) = make_float2(v2, v3);
            if (hOut){
                const size_t p0 = (size_t)(row0 >> 1)*2*Ncols + 2*col0 + (row0 & 1);
                const size_t p1 = (size_t)((row0+8) >> 1)*2*Ncols + 2*col0 + ((row0+8) & 1);
                hOut[p0]     = __float2half(v0);
                hOut[p0 + 2] = __float2half(v1);
                hOut[p1]     = __float2half(v2);
                hOut[p1 + 2] = __float2half(v3);
            }
        }
    }
}

// ---------------- per-node epilogue (padded float4 smem) ----------------
// sIn padded layout: [k=3][b=16][772 words: c*12+t (768) + 4 pad]
#define PB   772
#define PK   (16*PB)                 // 12352 words
#define EPI_IN_W   (3*PK)            // 37056
#define EPI_SMEM   ((EPI_IN_W + 12288 + 64) * (int)sizeof(float))  // 197,632 B

__global__ __launch_bounds__(256) void epilogue_kernel(
    const float* __restrict__ emb,
    const float* __restrict__ wsrc,
    const float* __restrict__ bsrc,
    float* __restrict__ out, int mode)
{
    extern __shared__ float sm[];
    float* sIn = sm;                 // EPI_IN_W (padded)
    float* sW  = sm + EPI_IN_W;      // 12288
    float* sB  = sW + 12288;         // 64
    const int n = blockIdx.x, tid = threadIdx.x;

    const float* s0 = g_Xr;
    const float* s1 = (mode == 0) ? g_G1 : g_D1;
    const float* s2 = (mode == 0) ? g_G2 : g_D2;
    const size_t off = (size_t)n * MC;

    for (int idx = tid; idx < 3*16*192; idx += 256){
        const int k   = idx / 3072;
        const int rem = idx - k*3072;
        const int b   = rem / 192;
        const int q   = rem - b*192;
        const float* srcp = (k == 0) ? s0 : (k == 1 ? s1 : s2);
        float4 v = ((const float4*)(srcp + off))[rem];
        ((float4*)sIn)[k*3088 + b*193 + q] = v;
    }
    if (mode == 0){
        float e[Ee];
#pragma unroll
        for (int d = 0; d < Ee; d++) e[d] = emb[n*Ee + d];
        for (int i = tid; i < 12288; i += 256){
            float s = 0.f;
#pragma unroll
            for (int d = 0; d < Ee; d++) s += e[d] * wsrc[d*12288 + i];
            sW[i] = s;
        }
        if (tid < Oo){
            float s = 0.f;
#pragma unroll
            for (int d = 0; d < Ee; d++) s += e[d] * bsrc[d*Oo + tid];
            sB[tid] = s;
        }
    } else {
        for (int i = tid; i < 12288; i += 256) sW[i] = wsrc[i];
        if (tid < Oo) sB[tid] = bsrc[tid];
    }
    __syncthreads();

    const int ty = tid >> 4, tx = tid & 15;   // tx = batch b, ty -> o group of 4
    const int oBase = ty * 4;

    unsigned long long acc[12][2];
#pragma unroll
    for (int t = 0; t < 12; t++){ acc[t][0] = 0ULL; acc[t][1] = 0ULL; }

    for (int kc = 0; kc < 192; kc++){
        const int k = kc >> 6;
        const int c = kc & 63;
        const float4* src = (const float4*)(sIn + k*PK + tx*PB + c*12);
        float4 v0 = src[0], v1 = src[1], v2 = src[2];
        const unsigned long long* wp = (const unsigned long long*)(sW + kc*64 + oBase);
        unsigned long long w01 = wp[0], w23 = wp[1];
        float tv[12] = {v0.x,v0.y,v0.z,v0.w, v1.x,v1.y,v1.z,v1.w, v2.x,v2.y,v2.z,v2.w};
#pragma unroll
        for (int t = 0; t < 12; t++){
            unsigned long long ap = pack_dup(tv[t]);
            fma2(acc[t][0], ap, w01);
            fma2(acc[t][1], ap, w23);
        }
    }

    float* outBase = out + (mode ? (size_t)XAV_SIZE : 0)
                   + (size_t)tx*ONT + (size_t)n*Tt;
#pragma unroll
    for (int j = 0; j < 4; j++){
        const float bia = sB[oBase + j];
        float v[12];
#pragma unroll
        for (int t = 0; t < 12; t++){
            float2 f = *reinterpret_cast<float2*>(&acc[t][j >> 1]);
            v[t] = ((j & 1) ? f.y : f.x) + bia;
        }
        float4* op = (float4*)(outBase + (size_t)(oBase + j)*NT);
        op[0] = make_float4(v[0], v[1], v[2],  v[3]);
        op[1] = make_float4(v[4], v[5], v[6],  v[7]);
        op[2] = make_float4(v[8], v[9], v[10], v[11]);
    }
}

// ---------------- launch ----------------
extern "C" void kernel_launch(void* const* d_in, const int* in_sizes, int n_in,
                              void* d_out, int out_size)
{
    const float* x     = (const float*)d_in[0];
    const float* emb   = (const float*)d_in[1];
    const float* sup   = (const float*)d_in[2];
    const float* wpool = (const float*)d_in[3];
    const float* bpool = (const float*)d_in[4];
    const float* mlp_w = (const float*)d_in[5];
    const float* mlp_b = (const float*)d_in[6];
    float* out = (float*)d_out;

    cudaFuncSetAttribute(epilogue_kernel, cudaFuncAttributeMaxDynamicSharedMemorySize, EPI_SMEM);
    cudaFuncSetAttribute(mma_gemm, cudaFuncAttributeMaxDynamicSharedMemorySize, GEMM_SMEM);

    __half *pAh, *pPTh;
    uint32_t *phXr, *phG1, *phD1;
    float *pXr, *pG1, *pG2, *pD1, *pD2;
    cudaGetSymbolAddress((void**)&pAh,  g_Ah);
    cudaGetSymbolAddress((void**)&pPTh, g_PTh);
    cudaGetSymbolAddress((void**)&phXr, g_hXr);
    cudaGetSymbolAddress((void**)&phG1, g_hG1);
    cudaGetSymbolAddress((void**)&phD1, g_hD1);
    cudaGetSymbolAddress((void**)&pXr,  g_Xr);
    cudaGetSymbolAddress((void**)&pG1,  g_G1);
    cudaGetSymbolAddress((void**)&pG2,  g_G2);
    cudaGetSymbolAddress((void**)&pD1,  g_D1);
    cudaGetSymbolAddress((void**)&pD2,  g_D2);

    // precompute
    compute_A_kernel<<<Nn, 256>>>(emb);
    transpose_X_kernel<<<(Nn/2*1024)/256, 256>>>(x);
    transpose2k_kernel<<<dim3(Nn/32, Nn/32), dim3(32, 8)>>>(sup, pPTh);

    // big GEMMs [2048 x 12288]
    dim3 gBig(MC/128, 16);
    // G1 = A @ Xr   (fp32 out for epilogue, packed-half out for G2 chain)
    mma_gemm<<<gBig, 256, GEMM_SMEM>>>(MC, 1.f, pAh, phXr, pG1,
                                       nullptr, 0.f, (__half*)phG1);
    // G2 = 2*A @ G1 - Xr   ( == (2A^2 - I) @ X )
    mma_gemm<<<gBig, 256, GEMM_SMEM>>>(MC, 2.f, pAh, phG1, pG2,
                                       pXr, -1.f, nullptr);
    // D1 = PT @ Xr
    mma_gemm<<<gBig, 256, GEMM_SMEM>>>(MC, 1.f, pPTh, phXr, pD1,
                                       nullptr, 0.f, (__half*)phD1);
    // D2 = PT @ D1
    mma_gemm<<<gBig, 256, GEMM_SMEM>>>(MC, 1.f, pPTh, phD1, pD2,
                                       nullptr, 0.f, nullptr);

    // epilogues
    epilogue_kernel<<<Nn, 256, EPI_SMEM>>>(emb, wpool, bpool, out, 0);
    epilogue_kernel<<<Nn, 256, EPI_SMEM>>>(emb, mlp_w, mlp_b, out, 1);
}

// round 13
// speedup vs baseline: 2.4890x; 1.3282x over previous
#include <cuda_runtime.h>
#include <cuda_fp16.h>
#include <cstdint>

// ---------------- problem constants ----------------
#define Nn   2048
#define Bb   16
#define Cc   64
#define Tt   12
#define Ee   10
#define Oo   64
#define MC   (Bb*Cc*Tt)        // 12288
#define NT   (Nn*Tt)           // 24576
#define ONT  (Oo*Nn*Tt)        // 1572864
#define XAV_SIZE (Bb*ONT)      // 25165824 floats

// Tiled packed-half layouts: word(tile, kpc, r, w) at ((tile*256 + kpc)*512 + r*4 + w)
// value = {M[2*(kpc*4+w)][tile*128+r], M[2*(kpc*4+w)+1][tile*128+r]} for B-side (k = row dim)
// value = {M[tile*128+r][2*(kpc*4+w)], M[tile*128+r][2*(kpc*4+w)+1]} for A-side (k = col dim)
#define TILE_WORDS 131072      // 256*512

// ---------------- scratch (device globals) ----------------
__device__ uint32_t g_Ah  [(size_t)16*TILE_WORDS];   // A tiled-packed (16 mtiles)
__device__ uint32_t g_PTh [(size_t)16*TILE_WORDS];
__device__ uint32_t g_hXr [(size_t)96*TILE_WORDS];   // B tiled-packed (96 ntiles)
__device__ uint32_t g_hG1 [(size_t)96*TILE_WORDS];
__device__ uint32_t g_hD1 [(size_t)96*TILE_WORDS];
__device__ float    g_Xr[(size_t)Nn*MC];
__device__ float    g_G1[(size_t)Nn*MC];
__device__ float    g_G2[(size_t)Nn*MC];
__device__ float    g_D1[(size_t)Nn*MC];
__device__ float    g_D2[(size_t)Nn*MC];

// ---------------- helpers ----------------
__device__ __forceinline__ uint32_t smem_u32(const void* p){
    uint32_t a;
    asm("{ .reg .u64 t; cvta.to.shared.u64 t, %1; cvt.u32.u64 %0, t; }" : "=r"(a) : "l"(p));
    return a;
}
__device__ __forceinline__ unsigned long long pack_dup(float a){
    unsigned long long r; asm("mov.b64 %0, {%1, %1};" : "=l"(r) : "f"(a)); return r;
}
__device__ __forceinline__ void fma2(unsigned long long &acc,
                                     unsigned long long a, unsigned long long b){
    asm("fma.rn.f32x2 %0, %1, %2, %0;" : "+l"(acc) : "l"(a), "l"(b));
}
__device__ __forceinline__ void mma_f16(float* d,
    uint32_t a0, uint32_t a1, uint32_t a2, uint32_t a3,
    uint32_t b0, uint32_t b1)
{
    asm volatile(
        "mma.sync.aligned.m16n8k16.row.col.f32.f16.f16.f32 "
        "{%0,%1,%2,%3}, {%4,%5,%6,%7}, {%8,%9}, {%0,%1,%2,%3};"
        : "+f"(d[0]), "+f"(d[1]), "+f"(d[2]), "+f"(d[3])
        : "r"(a0), "r"(a1), "r"(a2), "r"(a3), "r"(b0), "r"(b1));
}
__device__ __forceinline__ void ldmat4(uint32_t* r, uint32_t addr){
    asm volatile(
        "ldmatrix.sync.aligned.m8n8.x4.shared.b16 {%0,%1,%2,%3}, [%4];"
        : "=r"(r[0]), "=r"(r[1]), "=r"(r[2]), "=r"(r[3]) : "r"(addr));
}
__device__ __forceinline__ void cp16(uint32_t d, const void* s){
    asm volatile("cp.async.cg.shared.global [%0], [%1], 16;" :: "r"(d), "l"(s));
}
#define CP_COMMIT() asm volatile("cp.async.commit_group;" ::: "memory")
#define CP_WAIT2()  asm volatile("cp.async.wait_group 2;" ::: "memory")

__device__ __forceinline__ uint32_t pack2h(float lo, float hi){
    __half2 h = __floats2half2_rn(lo, hi);
    return *reinterpret_cast<uint32_t*>(&h);
}

// ---------------- A = rowsoftmax(relu(E E^T)) -> tiled packed half ----------------
__global__ __launch_bounds__(256) void compute_A_kernel(const float* __restrict__ emb)
{
    __shared__ float row[Nn];
    __shared__ float red[256];
    const int n = blockIdx.x, tid = threadIdx.x;
    float e[Ee];
#pragma unroll
    for (int d = 0; d < Ee; d++) e[d] = emb[n*Ee + d];
    float lmax = -1e30f;
    for (int m = tid; m < Nn; m += 256){
        float s = 0.f;
#pragma unroll
        for (int d = 0; d < Ee; d++) s += e[d] * emb[m*Ee + d];
        s = fmaxf(s, 0.f);
        row[m] = s; lmax = fmaxf(lmax, s);
    }
    red[tid] = lmax; __syncthreads();
    for (int s = 128; s > 0; s >>= 1){ if (tid < s) red[tid] = fmaxf(red[tid], red[tid+s]); __syncthreads(); }
    const float mx = red[0]; __syncthreads();
    float lsum = 0.f;
    for (int m = tid; m < Nn; m += 256){ float v = expf(row[m] - mx); row[m] = v; lsum += v; }
    red[tid] = lsum; __syncthreads();
    for (int s = 128; s > 0; s >>= 1){ if (tid < s) red[tid] += red[tid+s]; __syncthreads(); }
    const float inv = 1.f / red[0];
    // A-side tiled word (mtile = n>>7, r = n&127, k-pair i): {A[n][2i],A[n][2i+1]}
    const size_t base = ((size_t)(n >> 7)*256)*512 + (size_t)(n & 127)*4;
    for (int i = tid; i < 1024; i += 256){
        uint32_t w = pack2h(row[2*i]*inv, row[2*i+1]*inv);
        g_Ah[base + (size_t)(i >> 2)*512 + (i & 3)] = w;
    }
}

// ---- x[B,C,N,T] -> Xr fp32 [n][bc*12+t]  +  hXr tiled packed (B-side) ----
__global__ __launch_bounds__(256) void transpose_X_kernel(const float* __restrict__ x)
{
    const int g  = blockIdx.x * 256 + threadIdx.x;   // 0 .. 1024*1024-1
    const int bc = g >> 10;
    const int np = g & 1023;
    const int n0 = np*2;
    const float4* s0 = (const float4*)(x + ((size_t)bc*Nn + n0    ) * Tt);
    const float4* s1 = (const float4*)(x + ((size_t)bc*Nn + n0 + 1) * Tt);
    float4 a0 = s0[0], a1 = s0[1], a2 = s0[2];
    float4 b0 = s1[0], b1 = s1[1], b2 = s1[2];
    float4* d0 = (float4*)(g_Xr + (size_t)n0*MC + (size_t)bc*Tt);
    float4* d1 = (float4*)(g_Xr + (size_t)(n0+1)*MC + (size_t)bc*Tt);
    d0[0]=a0; d0[1]=a1; d0[2]=a2;
    d1[0]=b0; d1[1]=b1; d1[2]=b2;
    // packed words: (col = bc*12+t, kpair = np)
    float av[12] = {a0.x,a0.y,a0.z,a0.w, a1.x,a1.y,a1.z,a1.w, a2.x,a2.y,a2.z,a2.w};
    float bv[12] = {b0.x,b0.y,b0.z,b0.w, b1.x,b1.y,b1.z,b1.w, b2.x,b2.y,b2.z,b2.w};
    const size_t koff = (size_t)(np >> 2)*512 + (np & 3);
#pragma unroll
    for (int t = 0; t < 12; t++){
        const int col = bc*12 + t;
        g_hXr[((size_t)(col >> 7)*256)*512 + koff + (size_t)(col & 127)*4] = pack2h(av[t], bv[t]);
    }
}

// ---------------- PTh tiled packed: PT[m][k] = support[k][m] ----------------
__global__ void transpose2k_kernel(const float* __restrict__ S, uint32_t* __restrict__ D)
{
    __shared__ float tile[32][33];
    const int x0 = blockIdx.x*32, y0 = blockIdx.y*32;   // x: m, y: k
    const int tx = threadIdx.x, ty = threadIdx.y;       // (32,8)
#pragma unroll
    for (int j = 0; j < 4; j++)
        tile[ty + j*8][tx] = S[(size_t)(y0 + ty + j*8)*Nn + x0 + tx];
    __syncthreads();
    const int m = x0 + tx;
    const size_t mb = ((size_t)(m >> 7)*256)*512 + (size_t)(m & 127)*4;
#pragma unroll
    for (int j = 0; j < 2; j++){
        const int p = ty + j*8;            // local k-pair 0..15
        const int i = (y0 >> 1) + p;       // global k-pair
        D[mb + (size_t)(i >> 2)*512 + (i & 3)] = pack2h(tile[2*p][tx], tile[2*p+1][tx]);
    }
}

// ---------------- fp16 mma.sync GEMM, tiled operands, 4-stage cp.async ----------------
// smem stage: A [c=4][m=128][16B] (8KB) then B [c=4][n=128][16B] (8KB).
#define STAGE_BYTES 16384
#define GEMM_SMEM (4*STAGE_BYTES)       // 65536

__global__ __launch_bounds__(256, 2) void mma_gemm(
    int Ncols, float alpha,
    const uint32_t* __restrict__ At,    // tiled A-side
    const uint32_t* __restrict__ Bt,    // tiled B-side
    float* __restrict__ C,
    const float* __restrict__ Res, float beta,
    uint32_t* __restrict__ hOut)        // tiled B-side packed out (optional)
{
    extern __shared__ __align__(16) uint32_t smw[];
    const uint32_t sbase = smem_u32(smw);

    const int tid  = threadIdx.x;
    const int lane = tid & 31;
    const int wid  = tid >> 5;
    const int wm   = wid >> 1;          // 0..3
    const int wn   = wid & 1;           // 0..1
    const int gy   = lane >> 2;         // 0..7
    const int gx   = lane & 3;          // 0..3
    const int mat  = lane >> 3;         // 0..3
    const int mr   = lane & 7;

    const int nBase = blockIdx.x * 128;
    const int mBase = blockIdx.y * 128;

    const uint32_t* aG = At + (size_t)blockIdx.y*TILE_WORDS + tid*8;
    const uint32_t* bG = Bt + (size_t)blockIdx.x*TILE_WORDS + tid*8;

    // ldmatrix addresses (within a stage)
    const uint32_t aAddr0 = (uint32_t)((wm*32 + (mat & 1)*8 + mr)*16 + (mat >> 1)*2048);
    const uint32_t aAddr1 = aAddr0 + 256;   // +16 rows
    uint32_t bAddr[4];
#pragma unroll
    for (int q = 0; q < 4; q++)
        bAddr[q] = 8192 + (uint32_t)((wn*64 + q*16 + (mat >> 1)*8 + mr)*16 + (mat & 1)*2048);

#define ISSUE_STAGE(kt_) do { \
        uint32_t sb_ = sbase + ((kt_) & 3) * STAGE_BYTES; \
        const uint32_t* as_ = aG + (size_t)(kt_)*2048; \
        const uint32_t* bs_ = bG + (size_t)(kt_)*2048; \
        cp16(sb_ + tid*32,           as_); \
        cp16(sb_ + tid*32 + 16,      as_ + 4); \
        cp16(sb_ + 8192 + tid*32,    bs_); \
        cp16(sb_ + 8192 + tid*32+16, bs_ + 4); \
    } while(0)

    ISSUE_STAGE(0); CP_COMMIT();
    ISSUE_STAGE(1); CP_COMMIT();
    ISSUE_STAGE(2); CP_COMMIT();

    float acc[2][8][4];
#pragma unroll
    for (int mt = 0; mt < 2; mt++)
#pragma unroll
        for (int nt = 0; nt < 8; nt++)
#pragma unroll
            for (int r = 0; r < 4; r++) acc[mt][nt][r] = 0.f;

    const int NKT = 64;
    for (int kt = 0; kt < NKT; kt++){
        CP_WAIT2();
        __syncthreads();
        const int pf = kt + 3;
        if (pf < NKT) ISSUE_STAGE(pf);
        CP_COMMIT();

        const uint32_t so = sbase + (kt & 3) * STAGE_BYTES;
#pragma unroll
        for (int ks = 0; ks < 2; ks++){
            uint32_t a0[4], a1[4];
            ldmat4(a0, so + aAddr0 + ks*4096);
            ldmat4(a1, so + aAddr1 + ks*4096);
            uint32_t bb[4][4];
            ldmat4(bb[0], so + bAddr[0] + ks*4096);
            ldmat4(bb[1], so + bAddr[1] + ks*4096);
            ldmat4(bb[2], so + bAddr[2] + ks*4096);
            ldmat4(bb[3], so + bAddr[3] + ks*4096);
#pragma unroll
            for (int nt = 0; nt < 8; nt++){
                const uint32_t b0 = bb[nt >> 1][(nt & 1)*2];
                const uint32_t b1 = bb[nt >> 1][(nt & 1)*2 + 1];
                mma_f16(acc[0][nt], a0[0], a0[1], a0[2], a0[3], b0, b1);
                mma_f16(acc[1][nt], a1[0], a1[1], a1[2], a1[3], b0, b1);
            }
        }
    }
#undef ISSUE_STAGE

    // writeout
#pragma unroll
    for (int mt = 0; mt < 2; mt++){
#pragma unroll
        for (int nt = 0; nt < 8; nt++){
            const int row0 = mBase + wm*32 + mt*16 + gy;
            const int col0 = nBase + wn*64 + nt*8 + gx*2;
            float v0 = acc[mt][nt][0] * alpha;
            float v1 = acc[mt][nt][1] * alpha;
            float v2 = acc[mt][nt][2] * alpha;
            float v3 = acc[mt][nt][3] * alpha;
            if (Res){
                float2 r0 = *(const float2*)(Res + (size_t)row0    *Ncols + col0);
                float2 r1 = *(const float2*)(Res + (size_t)(row0+8)*Ncols + col0);
                v0 += beta * r0.x; v1 += beta * r0.y;
                v2 += beta * r1.x; v3 += beta * r1.y;
            }
            *(float2*)(C + (size_t)row0    *Ncols + col0) = make_float2(v0, v1);
            *(float2*)(C + (size_t)(row0+8)*Ncols + col0) = make_float2(v2, v3);
            if (hOut){
                // rows (row0, row0^1) live in lanes (lane, lane^4): build pair words
                float p0 = __shfl_xor_sync(0xffffffffu, v0, 4);
                float p1 = __shfl_xor_sync(0xffffffffu, v1, 4);
                float p2 = __shfl_xor_sync(0xffffffffu, v2, 4);
                float p3 = __shfl_xor_sync(0xffffffffu, v3, 4);
                if (!(gy & 1)){
                    const int kp = row0 >> 1;          // row0 even
                    const size_t cb0 = ((size_t)(col0 >> 7)*256)*512 + (size_t)(col0 & 127)*4;
                    const size_t cb1 = ((size_t)((col0+1) >> 7)*256)*512 + (size_t)((col0+1) & 127)*4;
                    const size_t k0 = (size_t)(kp >> 2)*512 + (kp & 3);
                    const size_t k1 = k0 + 512;       // kp+4 -> kpc+1, same w
                    hOut[cb0 + k0] = pack2h(v0, p0);
                    hOut[cb1 + k0] = pack2h(v1, p1);
                    hOut[cb0 + k1] = pack2h(v2, p2);
                    hOut[cb1 + k1] = pack2h(v3, p3);
                }
            }
        }
    }
}

// ---------------- per-node epilogue (padded float4 smem) ----------------
#define PB   772
#define PK   (16*PB)
#define EPI_IN_W   (3*PK)
#define EPI_SMEM   ((EPI_IN_W + 12288 + 64) * (int)sizeof(float))

__global__ __launch_bounds__(256) void epilogue_kernel(
    const float* __restrict__ emb,
    const float* __restrict__ wsrc,
    const float* __restrict__ bsrc,
    float* __restrict__ out, int mode)
{
    extern __shared__ float sm[];
    float* sIn = sm;
    float* sW  = sm + EPI_IN_W;
    float* sB  = sW + 12288;
    const int n = blockIdx.x, tid = threadIdx.x;

    const float* s0 = g_Xr;
    const float* s1 = (mode == 0) ? g_G1 : g_D1;
    const float* s2 = (mode == 0) ? g_G2 : g_D2;
    const size_t off = (size_t)n * MC;

    for (int idx = tid; idx < 3*16*192; idx += 256){
        const int k   = idx / 3072;
        const int rem = idx - k*3072;
        const int b   = rem / 192;
        const int q   = rem - b*192;
        const float* srcp = (k == 0) ? s0 : (k == 1 ? s1 : s2);
        float4 v = ((const float4*)(srcp + off))[rem];
        ((float4*)sIn)[k*3088 + b*193 + q] = v;
    }
    if (mode == 0){
        float e[Ee];
#pragma unroll
        for (int d = 0; d < Ee; d++) e[d] = emb[n*Ee + d];
        for (int i = tid; i < 12288; i += 256){
            float s = 0.f;
#pragma unroll
            for (int d = 0; d < Ee; d++) s += e[d] * wsrc[d*12288 + i];
            sW[i] = s;
        }
        if (tid < Oo){
            float s = 0.f;
#pragma unroll
            for (int d = 0; d < Ee; d++) s += e[d] * bsrc[d*Oo + tid];
            sB[tid] = s;
        }
    } else {
        for (int i = tid; i < 12288; i += 256) sW[i] = wsrc[i];
        if (tid < Oo) sB[tid] = bsrc[tid];
    }
    __syncthreads();

    const int ty = tid >> 4, tx = tid & 15;
    const int oBase = ty * 4;

    unsigned long long acc[12][2];
#pragma unroll
    for (int t = 0; t < 12; t++){ acc[t][0] = 0ULL; acc[t][1] = 0ULL; }

    for (int kc = 0; kc < 192; kc++){
        const int k = kc >> 6;
        const int c = kc & 63;
        const float4* src = (const float4*)(sIn + k*PK + tx*PB + c*12);
        float4 v0 = src[0], v1 = src[1], v2 = src[2];
        const unsigned long long* wp = (const unsigned long long*)(sW + kc*64 + oBase);
        unsigned long long w01 = wp[0], w23 = wp[1];
        float tv[12] = {v0.x,v0.y,v0.z,v0.w, v1.x,v1.y,v1.z,v1.w, v2.x,v2.y,v2.z,v2.w};
#pragma unroll
        for (int t = 0; t < 12; t++){
            unsigned long long ap = pack_dup(tv[t]);
            fma2(acc[t][0], ap, w01);
            fma2(acc[t][1], ap, w23);
        }
    }

    float* outBase = out + (mode ? (size_t)XAV_SIZE : 0)
                   + (size_t)tx*ONT + (size_t)n*Tt;
#pragma unroll
    for (int j = 0; j < 4; j++){
        const float bia = sB[oBase + j];
        float v[12];
#pragma unroll
        for (int t = 0; t < 12; t++){
            float2 f = *reinterpret_cast<float2*>(&acc[t][j >> 1]);
            v[t] = ((j & 1) ? f.y : f.x) + bia;
        }
        float4* op = (float4*)(outBase + (size_t)(oBase + j)*NT);
        op[0] = make_float4(v[0], v[1], v[2],  v[3]);
        op[1] = make_float4(v[4], v[5], v[6],  v[7]);
        op[2] = make_float4(v[8], v[9], v[10], v[11]);
    }
}

// ---------------- launch ----------------
extern "C" void kernel_launch(void* const* d_in, const int* in_sizes, int n_in,
                              void* d_out, int out_size)
{
    const float* x     = (const float*)d_in[0];
    const float* emb   = (const float*)d_in[1];
    const float* sup   = (const float*)d_in[2];
    const float* wpool = (const float*)d_in[3];
    const float* bpool = (const float*)d_in[4];
    const float* mlp_w = (const float*)d_in[5];
    const float* mlp_b = (const float*)d_in[6];
    float* out = (float*)d_out;

    cudaFuncSetAttribute(epilogue_kernel, cudaFuncAttributeMaxDynamicSharedMemorySize, EPI_SMEM);
    cudaFuncSetAttribute(mma_gemm, cudaFuncAttributeMaxDynamicSharedMemorySize, GEMM_SMEM);

    uint32_t *pAh, *pPTh, *phXr, *phG1, *phD1;
    float *pXr, *pG1, *pG2, *pD1, *pD2;
    cudaGetSymbolAddress((void**)&pAh,  g_Ah);
    cudaGetSymbolAddress((void**)&pPTh, g_PTh);
    cudaGetSymbolAddress((void**)&phXr, g_hXr);
    cudaGetSymbolAddress((void**)&phG1, g_hG1);
    cudaGetSymbolAddress((void**)&phD1, g_hD1);
    cudaGetSymbolAddress((void**)&pXr,  g_Xr);
    cudaGetSymbolAddress((void**)&pG1,  g_G1);
    cudaGetSymbolAddress((void**)&pG2,  g_G2);
    cudaGetSymbolAddress((void**)&pD1,  g_D1);
    cudaGetSymbolAddress((void**)&pD2,  g_D2);

    // precompute
    compute_A_kernel<<<Nn, 256>>>(emb);
    transpose_X_kernel<<<4096, 256>>>(x);
    transpose2k_kernel<<<dim3(Nn/32, Nn/32), dim3(32, 8)>>>(sup, pPTh);

    // big GEMMs [2048 x 12288]
    dim3 gBig(MC/128, 16);
    // G1 = A @ Xr   (fp32 out for epilogue, tiled-packed-half out for G2 chain)
    mma_gemm<<<gBig, 256, GEMM_SMEM>>>(MC, 1.f, pAh, phXr, pG1, nullptr, 0.f, phG1);
    // G2 = 2*A @ G1 - Xr   ( == (2A^2 - I) @ X )
    mma_gemm<<<gBig, 256, GEMM_SMEM>>>(MC, 2.f, pAh, phG1, pG2, pXr, -1.f, nullptr);
    // D1 = PT @ Xr
    mma_gemm<<<gBig, 256, GEMM_SMEM>>>(MC, 1.f, pPTh, phXr, pD1, nullptr, 0.f, phD1);
    // D2 = PT @ D1
    mma_gemm<<<gBig, 256, GEMM_SMEM>>>(MC, 1.f, pPTh, phD1, pD2, nullptr, 0.f, nullptr);

    // epilogues
    epilogue_kernel<<<Nn, 256, EPI_SMEM>>>(emb, wpool, bpool, out, 0);
    epilogue_kernel<<<Nn, 256, EPI_SMEM>>>(emb, mlp_w, mlp_b, out, 1);
}

// round 15
// speedup vs baseline: 3.4667x; 1.3928x over previous
#include <cuda_runtime.h>
#include <cuda_fp16.h>
#include <cstdint>

// ---------------- problem constants ----------------
#define Nn   2048
#define Bb   16
#define Cc   64
#define Tt   12
#define Ee   10
#define Oo   64
#define MC   (Bb*Cc*Tt)        // 12288
#define NT   (Nn*Tt)           // 24576
#define ONT  (Oo*Nn*Tt)        // 1572864
#define XAV_SIZE (Bb*ONT)      // 25165824 floats

#define TILE_WORDS 131072      // 256*512 (tiled packed-half operand layout)

// ---------------- scratch (device globals) ----------------
__device__ uint32_t g_Ah  [(size_t)16*TILE_WORDS];   // A tiled-packed
__device__ uint32_t g_PTh [(size_t)16*TILE_WORDS];
__device__ uint32_t g_hXr [(size_t)96*TILE_WORDS];   // B tiled-packed
__device__ uint32_t g_hG1 [(size_t)96*TILE_WORDS];
__device__ uint32_t g_hD1 [(size_t)96*TILE_WORDS];
__device__ __half   g_Xh [(size_t)Nn*MC];            // half row-major [node][col]
__device__ __half   g_G1h[(size_t)Nn*MC];
__device__ __half   g_G2h[(size_t)Nn*MC];
__device__ __half   g_D1h[(size_t)Nn*MC];
__device__ __half   g_D2h[(size_t)Nn*MC];

// ---------------- helpers ----------------
__device__ __forceinline__ uint32_t smem_u32(const void* p){
    uint32_t a;
    asm("{ .reg .u64 t; cvta.to.shared.u64 t, %1; cvt.u32.u64 %0, t; }" : "=r"(a) : "l"(p));
    return a;
}
__device__ __forceinline__ void mma_f16(float* d,
    uint32_t a0, uint32_t a1, uint32_t a2, uint32_t a3,
    uint32_t b0, uint32_t b1)
{
    asm volatile(
        "mma.sync.aligned.m16n8k16.row.col.f32.f16.f16.f32 "
        "{%0,%1,%2,%3}, {%4,%5,%6,%7}, {%8,%9}, {%0,%1,%2,%3};"
        : "+f"(d[0]), "+f"(d[1]), "+f"(d[2]), "+f"(d[3])
        : "r"(a0), "r"(a1), "r"(a2), "r"(a3), "r"(b0), "r"(b1));
}
__device__ __forceinline__ void ldmat4(uint32_t* r, uint32_t addr){
    asm volatile(
        "ldmatrix.sync.aligned.m8n8.x4.shared.b16 {%0,%1,%2,%3}, [%4];"
        : "=r"(r[0]), "=r"(r[1]), "=r"(r[2]), "=r"(r[3]) : "r"(addr));
}
__device__ __forceinline__ void ldmat4t(uint32_t* r, uint32_t addr){
    asm volatile(
        "ldmatrix.sync.aligned.m8n8.x4.trans.shared.b16 {%0,%1,%2,%3}, [%4];"
        : "=r"(r[0]), "=r"(r[1]), "=r"(r[2]), "=r"(r[3]) : "r"(addr));
}
__device__ __forceinline__ void cp16(uint32_t d, const void* s){
    asm volatile("cp.async.cg.shared.global [%0], [%1], 16;" :: "r"(d), "l"(s));
}
#define CP_COMMIT() asm volatile("cp.async.commit_group;" ::: "memory")
#define CP_WAIT2()  asm volatile("cp.async.wait_group 2;" ::: "memory")

__device__ __forceinline__ uint32_t pack2h(float lo, float hi){
    __half2 h = __floats2half2_rn(lo, hi);
    return *reinterpret_cast<uint32_t*>(&h);
}

// ---------------- A = rowsoftmax(relu(E E^T)) -> tiled packed half ----------------
__global__ __launch_bounds__(256) void compute_A_kernel(const float* __restrict__ emb)
{
    __shared__ float row[Nn];
    __shared__ float red[256];
    const int n = blockIdx.x, tid = threadIdx.x;
    float e[Ee];
#pragma unroll
    for (int d = 0; d < Ee; d++) e[d] = emb[n*Ee + d];
    float lmax = -1e30f;
    for (int m = tid; m < Nn; m += 256){
        float s = 0.f;
#pragma unroll
        for (int d = 0; d < Ee; d++) s += e[d] * emb[m*Ee + d];
        s = fmaxf(s, 0.f);
        row[m] = s; lmax = fmaxf(lmax, s);
    }
    red[tid] = lmax; __syncthreads();
    for (int s = 128; s > 0; s >>= 1){ if (tid < s) red[tid] = fmaxf(red[tid], red[tid+s]); __syncthreads(); }
    const float mx = red[0]; __syncthreads();
    float lsum = 0.f;
    for (int m = tid; m < Nn; m += 256){ float v = expf(row[m] - mx); row[m] = v; lsum += v; }
    red[tid] = lsum; __syncthreads();
    for (int s = 128; s > 0; s >>= 1){ if (tid < s) red[tid] += red[tid+s]; __syncthreads(); }
    const float inv = 1.f / red[0];
    const size_t base = ((size_t)(n >> 7)*256)*512 + (size_t)(n & 127)*4;
    for (int i = tid; i < 1024; i += 256){
        uint32_t w = pack2h(row[2*i]*inv, row[2*i+1]*inv);
        g_Ah[base + (size_t)(i >> 2)*512 + (i & 3)] = w;
    }
}

// ---- x[B,C,N,T] -> Xh half row-major [n][bc*12+t] + hXr tiled packed ----
__global__ __launch_bounds__(256) void transpose_X_kernel(const float* __restrict__ x)
{
    const int g  = blockIdx.x * 256 + threadIdx.x;   // 0 .. 1024*1024-1
    const int bc = g >> 10;
    const int np = g & 1023;
    const int n0 = np*2;
    const float4* s0 = (const float4*)(x + ((size_t)bc*Nn + n0    ) * Tt);
    const float4* s1 = (const float4*)(x + ((size_t)bc*Nn + n0 + 1) * Tt);
    float4 a0 = s0[0], a1 = s0[1], a2 = s0[2];
    float4 b0 = s1[0], b1 = s1[1], b2 = s1[2];
    float av[12] = {a0.x,a0.y,a0.z,a0.w, a1.x,a1.y,a1.z,a1.w, a2.x,a2.y,a2.z,a2.w};
    float bv[12] = {b0.x,b0.y,b0.z,b0.w, b1.x,b1.y,b1.z,b1.w, b2.x,b2.y,b2.z,b2.w};
    // row-major half rows n0, n0+1
    uint2* d0 = (uint2*)(g_Xh + (size_t)n0*MC + (size_t)bc*Tt);
    uint2* d1 = (uint2*)(g_Xh + (size_t)(n0+1)*MC + (size_t)bc*Tt);
    d0[0] = make_uint2(pack2h(av[0],av[1]),  pack2h(av[2],av[3]));
    d0[1] = make_uint2(pack2h(av[4],av[5]),  pack2h(av[6],av[7]));
    d0[2] = make_uint2(pack2h(av[8],av[9]),  pack2h(av[10],av[11]));
    d1[0] = make_uint2(pack2h(bv[0],bv[1]),  pack2h(bv[2],bv[3]));
    d1[1] = make_uint2(pack2h(bv[4],bv[5]),  pack2h(bv[6],bv[7]));
    d1[2] = make_uint2(pack2h(bv[8],bv[9]),  pack2h(bv[10],bv[11]));
    // tiled packed words (col = bc*12+t, kpair = np)
    const size_t koff = (size_t)(np >> 2)*512 + (np & 3);
#pragma unroll
    for (int t = 0; t < 12; t++){
        const int col = bc*12 + t;
        g_hXr[((size_t)(col >> 7)*256)*512 + koff + (size_t)(col & 127)*4] = pack2h(av[t], bv[t]);
    }
}

// ---------------- PTh tiled packed: PT[m][k] = support[k][m] ----------------
__global__ void transpose2k_kernel(const float* __restrict__ S, uint32_t* __restrict__ D)
{
    __shared__ float tile[32][33];
    const int x0 = blockIdx.x*32, y0 = blockIdx.y*32;   // x: m, y: k
    const int tx = threadIdx.x, ty = threadIdx.y;       // (32,8)
#pragma unroll
    for (int j = 0; j < 4; j++)
        tile[ty + j*8][tx] = S[(size_t)(y0 + ty + j*8)*Nn + x0 + tx];
    __syncthreads();
    const int m = x0 + tx;
    const size_t mb = ((size_t)(m >> 7)*256)*512 + (size_t)(m & 127)*4;
#pragma unroll
    for (int j = 0; j < 2; j++){
        const int p = ty + j*8;
        const int i = (y0 >> 1) + p;
        D[mb + (size_t)(i >> 2)*512 + (i & 3)] = pack2h(tile[2*p][tx], tile[2*p+1][tx]);
    }
}

// ---------------- fp16 mma.sync GEMM, tiled operands, 4-stage cp.async ----------------
#define STAGE_BYTES 16384
#define GEMM_SMEM (4*STAGE_BYTES)

__global__ __launch_bounds__(256, 2) void mma_gemm(
    int Ncols, float alpha,
    const uint32_t* __restrict__ At,
    const uint32_t* __restrict__ Bt,
    __half* __restrict__ Ch,            // half row-major output
    const __half* __restrict__ ResH, float beta,
    uint32_t* __restrict__ hOut)        // tiled packed out (optional)
{
    extern __shared__ __align__(16) uint32_t smw[];
    const uint32_t sbase = smem_u32(smw);

    const int tid  = threadIdx.x;
    const int lane = tid & 31;
    const int wid  = tid >> 5;
    const int wm   = wid >> 1;
    const int wn   = wid & 1;
    const int gy   = lane >> 2;
    const int gx   = lane & 3;
    const int mat  = lane >> 3;
    const int mr   = lane & 7;

    const int nBase = blockIdx.x * 128;
    const int mBase = blockIdx.y * 128;

    const uint32_t* aG = At + (size_t)blockIdx.y*TILE_WORDS + tid*8;
    const uint32_t* bG = Bt + (size_t)blockIdx.x*TILE_WORDS + tid*8;

    const uint32_t aAddr0 = (uint32_t)((wm*32 + (mat & 1)*8 + mr)*16 + (mat >> 1)*2048);
    const uint32_t aAddr1 = aAddr0 + 256;
    uint32_t bAddr[4];
#pragma unroll
    for (int q = 0; q < 4; q++)
        bAddr[q] = 8192 + (uint32_t)((wn*64 + q*16 + (mat >> 1)*8 + mr)*16 + (mat & 1)*2048);

#define ISSUE_STAGE(kt_) do { \
        uint32_t sb_ = sbase + ((kt_) & 3) * STAGE_BYTES; \
        const uint32_t* as_ = aG + (size_t)(kt_)*2048; \
        const uint32_t* bs_ = bG + (size_t)(kt_)*2048; \
        cp16(sb_ + tid*32,           as_); \
        cp16(sb_ + tid*32 + 16,      as_ + 4); \
        cp16(sb_ + 8192 + tid*32,    bs_); \
        cp16(sb_ + 8192 + tid*32+16, bs_ + 4); \
    } while(0)

    ISSUE_STAGE(0); CP_COMMIT();
    ISSUE_STAGE(1); CP_COMMIT();
    ISSUE_STAGE(2); CP_COMMIT();

    float acc[2][8][4];
#pragma unroll
    for (int mt = 0; mt < 2; mt++)
#pragma unroll
        for (int nt = 0; nt < 8; nt++)
#pragma unroll
            for (int r = 0; r < 4; r++) acc[mt][nt][r] = 0.f;

    const int NKT = 64;
    for (int kt = 0; kt < NKT; kt++){
        CP_WAIT2();
        __syncthreads();
        const int pf = kt + 3;
        if (pf < NKT) ISSUE_STAGE(pf);
        CP_COMMIT();

        const uint32_t so = sbase + (kt & 3) * STAGE_BYTES;
#pragma unroll
        for (int ks = 0; ks < 2; ks++){
            uint32_t a0[4], a1[4];
            ldmat4(a0, so + aAddr0 + ks*4096);
            ldmat4(a1, so + aAddr1 + ks*4096);
            uint32_t bb[4][4];
            ldmat4(bb[0], so + bAddr[0] + ks*4096);
            ldmat4(bb[1], so + bAddr[1] + ks*4096);
            ldmat4(bb[2], so + bAddr[2] + ks*4096);
            ldmat4(bb[3], so + bAddr[3] + ks*4096);
#pragma unroll
            for (int nt = 0; nt < 8; nt++){
                const uint32_t b0 = bb[nt >> 1][(nt & 1)*2];
                const uint32_t b1 = bb[nt >> 1][(nt & 1)*2 + 1];
                mma_f16(acc[0][nt], a0[0], a0[1], a0[2], a0[3], b0, b1);
                mma_f16(acc[1][nt], a1[0], a1[1], a1[2], a1[3], b0, b1);
            }
        }
    }
#undef ISSUE_STAGE

#pragma unroll
    for (int mt = 0; mt < 2; mt++){
#pragma unroll
        for (int nt = 0; nt < 8; nt++){
            const int row0 = mBase + wm*32 + mt*16 + gy;
            const int col0 = nBase + wn*64 + nt*8 + gx*2;
            float v0 = acc[mt][nt][0] * alpha;
            float v1 = acc[mt][nt][1] * alpha;
            float v2 = acc[mt][nt][2] * alpha;
            float v3 = acc[mt][nt][3] * alpha;
            if (ResH){
                __half2 r0 = *(const __half2*)(ResH + (size_t)row0    *Ncols + col0);
                __half2 r1 = *(const __half2*)(ResH + (size_t)(row0+8)*Ncols + col0);
                float2 f0 = __half22float2(r0), f1 = __half22float2(r1);
                v0 += beta * f0.x; v1 += beta * f0.y;
                v2 += beta * f1.x; v3 += beta * f1.y;
            }
            *(__half2*)(Ch + (size_t)row0    *Ncols + col0) = __floats2half2_rn(v0, v1);
            *(__half2*)(Ch + (size_t)(row0+8)*Ncols + col0) = __floats2half2_rn(v2, v3);
            if (hOut){
                float p0 = __shfl_xor_sync(0xffffffffu, v0, 4);
                float p1 = __shfl_xor_sync(0xffffffffu, v1, 4);
                float p2 = __shfl_xor_sync(0xffffffffu, v2, 4);
                float p3 = __shfl_xor_sync(0xffffffffu, v3, 4);
                if (!(gy & 1)){
                    const int kp = row0 >> 1;
                    const size_t cb0 = ((size_t)(col0 >> 7)*256)*512 + (size_t)(col0 & 127)*4;
                    const size_t cb1 = ((size_t)((col0+1) >> 7)*256)*512 + (size_t)((col0+1) & 127)*4;
                    const size_t k0 = (size_t)(kp >> 2)*512 + (kp & 3);
                    const size_t k1 = k0 + 512;
                    hOut[cb0 + k0] = pack2h(v0, p0);
                    hOut[cb1 + k0] = pack2h(v1, p1);
                    hOut[cb0 + k1] = pack2h(v2, p2);
                    hOut[cb1 + k1] = pack2h(v3, p3);
                }
            }
        }
    }
}

// ---------------- per-node epilogue via tensor cores ----------------
// Out[r=(b*12+t)][o] = sum_k In[r][k] * W[k][o] + bias[o],  R=192, K=192, O=64
#define KS 200    // sA row stride (halves)
#define WS 72     // sW row stride (halves)
#define OS 72     // sOut row stride (floats)
#define SA_BYTES   (192*KS*2)            // 76800
#define SW_BYTES   (192*WS*2)            // 27648
#define SB_OFF     (SA_BYTES + SW_BYTES) // 104448
#define SOUT_OFF   (SB_OFF + 256)        // 104704
#define EPI_SMEM   (SOUT_OFF + 192*OS*4) // 160000

__global__ __launch_bounds__(512) void epilogue_kernel(
    const float* __restrict__ emb,
    const float* __restrict__ wsrc,
    const float* __restrict__ bsrc,
    float* __restrict__ out, int mode)
{
    extern __shared__ __align__(16) char smc[];
    __half* sA   = (__half*)smc;
    __half* sW   = (__half*)(smc + SA_BYTES);
    float*  sB   = (float*)(smc + SB_OFF);
    float*  sOut = (float*)(smc + SOUT_OFF);
    const int n = blockIdx.x, tid = threadIdx.x;

    const __half* s0 = g_Xh  + (size_t)n*MC;
    const __half* s1 = ((mode == 0) ? g_G1h : g_D1h) + (size_t)n*MC;
    const __half* s2 = ((mode == 0) ? g_G2h : g_D2h) + (size_t)n*MC;

    // fill sA[(b*12+t)*KS + s*64+c] from src_s[b*768 + c*12 + t]
    for (int u = tid; u < 3072; u += 512){
        const int s = u >> 10;
        const int rem = u & 1023;
        const int b = rem >> 6, c = rem & 63;
        const __half* src = (s == 0 ? s0 : (s == 1 ? s1 : s2)) + b*768 + c*12;
        uint2 q0 = ((const uint2*)src)[0];
        uint2 q1 = ((const uint2*)src)[1];
        uint2 q2 = ((const uint2*)src)[2];
        uint32_t w[6] = {q0.x, q0.y, q1.x, q1.y, q2.x, q2.y};
        __half* dst = sA + (b*12)*KS + s*64 + c;
#pragma unroll
        for (int j = 0; j < 6; j++){
            __half2 hh = *(__half2*)&w[j];
            dst[(2*j  )*KS] = __low2half(hh);
            dst[(2*j+1)*KS] = __high2half(hh);
        }
    }
    // fill sW[k*WS + o] (half) and sB
    if (mode == 0){
        float e[Ee];
#pragma unroll
        for (int d = 0; d < Ee; d++) e[d] = emb[n*Ee + d];
        for (int i = tid; i < 12288; i += 512){
            float s = 0.f;
#pragma unroll
            for (int d = 0; d < Ee; d++) s += e[d] * wsrc[d*12288 + i];
            sW[(i >> 6)*WS + (i & 63)] = __float2half(s);
        }
        if (tid < Oo){
            float s = 0.f;
#pragma unroll
            for (int d = 0; d < Ee; d++) s += e[d] * bsrc[d*Oo + tid];
            sB[tid] = s;
        }
    } else {
        for (int i = tid; i < 12288; i += 512)
            sW[(i >> 6)*WS + (i & 63)] = __float2half(wsrc[i]);
        if (tid < Oo) sB[tid] = bsrc[tid];
    }
    __syncthreads();

    // mma: 16 warps = 4(m: 48 rows) x 4(n: 16 cols)
    const int warp = tid >> 5, lane = tid & 31;
    const int mw = warp >> 2, nw = warp & 3;
    const int grp = lane >> 3, lr = lane & 7;
    const int gy = lane >> 2, gx = lane & 3;

    uint32_t aOff[3];
#pragma unroll
    for (int mt = 0; mt < 3; mt++)
        aOff[mt] = smem_u32(sA + (mw*48 + mt*16 + (grp & 1)*8 + lr)*KS) + (grp >> 1)*16;
    const uint32_t bOff = smem_u32(sW + ((grp & 1)*8 + lr)*WS + nw*16 + (grp >> 1)*8);

    float acc[3][2][4];
#pragma unroll
    for (int mt = 0; mt < 3; mt++)
#pragma unroll
        for (int nt = 0; nt < 2; nt++)
#pragma unroll
            for (int r = 0; r < 4; r++) acc[mt][nt][r] = 0.f;

#pragma unroll
    for (int ks = 0; ks < 12; ks++){
        uint32_t bf[4];
        ldmat4t(bf, bOff + ks*(16*WS*2));
#pragma unroll
        for (int mt = 0; mt < 3; mt++){
            uint32_t af[4];
            ldmat4(af, aOff[mt] + ks*32);
            mma_f16(acc[mt][0], af[0], af[1], af[2], af[3], bf[0], bf[1]);
            mma_f16(acc[mt][1], af[0], af[1], af[2], af[3], bf[2], bf[3]);
        }
    }

    // stage result to sOut
#pragma unroll
    for (int mt = 0; mt < 3; mt++){
#pragma unroll
        for (int nt = 0; nt < 2; nt++){
            const int r0 = mw*48 + mt*16 + gy;
            const int cb = nw*16 + nt*8 + gx*2;
            *(float2*)(sOut + r0*OS + cb)     = make_float2(acc[mt][nt][0], acc[mt][nt][1]);
            *(float2*)(sOut + (r0+8)*OS + cb) = make_float2(acc[mt][nt][2], acc[mt][nt][3]);
        }
    }
    __syncthreads();

    // coalesced writeback: units (b,o)
    float* outBase = out + (mode ? (size_t)XAV_SIZE : 0);
    for (int u = tid; u < 1024; u += 512){
        const int b = u >> 6, o = u & 63;
        const float bia = sB[o];
        float v[12];
#pragma unroll
        for (int t = 0; t < 12; t++) v[t] = sOut[(b*12 + t)*OS + o] + bia;
        float4* op = (float4*)(outBase + (size_t)b*ONT + (size_t)o*NT + (size_t)n*Tt);
        op[0] = make_float4(v[0], v[1], v[2],  v[3]);
        op[1] = make_float4(v[4], v[5], v[6],  v[7]);
        op[2] = make_float4(v[8], v[9], v[10], v[11]);
    }
}

// ---------------- launch ----------------
extern "C" void kernel_launch(void* const* d_in, const int* in_sizes, int n_in,
                              void* d_out, int out_size)
{
    const float* x     = (const float*)d_in[0];
    const float* emb   = (const float*)d_in[1];
    const float* sup   = (const float*)d_in[2];
    const float* wpool = (const float*)d_in[3];
    const float* bpool = (const float*)d_in[4];
    const float* mlp_w = (const float*)d_in[5];
    const float* mlp_b = (const float*)d_in[6];
    float* out = (float*)d_out;

    cudaFuncSetAttribute(epilogue_kernel, cudaFuncAttributeMaxDynamicSharedMemorySize, EPI_SMEM);
    cudaFuncSetAttribute(mma_gemm, cudaFuncAttributeMaxDynamicSharedMemorySize, GEMM_SMEM);

    uint32_t *pAh, *pPTh, *phXr, *phG1, *phD1;
    __half *pXh, *pG1h, *pG2h, *pD1h, *pD2h;
    cudaGetSymbolAddress((void**)&pAh,  g_Ah);
    cudaGetSymbolAddress((void**)&pPTh, g_PTh);
    cudaGetSymbolAddress((void**)&phXr, g_hXr);
    cudaGetSymbolAddress((void**)&phG1, g_hG1);
    cudaGetSymbolAddress((void**)&phD1, g_hD1);
    cudaGetSymbolAddress((void**)&pXh,  g_Xh);
    cudaGetSymbolAddress((void**)&pG1h, g_G1h);
    cudaGetSymbolAddress((void**)&pG2h, g_G2h);
    cudaGetSymbolAddress((void**)&pD1h, g_D1h);
    cudaGetSymbolAddress((void**)&pD2h, g_D2h);

    // precompute
    compute_A_kernel<<<Nn, 256>>>(emb);
    transpose_X_kernel<<<4096, 256>>>(x);
    transpose2k_kernel<<<dim3(Nn/32, Nn/32), dim3(32, 8)>>>(sup, pPTh);

    // big GEMMs [2048 x 12288]
    dim3 gBig(MC/128, 16);
    // G1 = A @ X   (row-half for epilogue, tiled-half for G2 chain)
    mma_gemm<<<gBig, 256, GEMM_SMEM>>>(MC, 1.f, pAh, phXr, pG1h, nullptr, 0.f, phG1);
    // G2 = 2*A @ G1 - X
    mma_gemm<<<gBig, 256, GEMM_SMEM>>>(MC, 2.f, pAh, phG1, pG2h, pXh, -1.f, nullptr);
    // D1 = PT @ X
    mma_gemm<<<gBig, 256, GEMM_SMEM>>>(MC, 1.f, pPTh, phXr, pD1h, nullptr, 0.f, phD1);
    // D2 = PT @ D1
    mma_gemm<<<gBig, 256, GEMM_SMEM>>>(MC, 1.f, pPTh, phD1, pD2h, nullptr, 0.f, nullptr);

    // epilogues (tensor-core)
    epilogue_kernel<<<Nn, 512, EPI_SMEM>>>(emb, wpool, bpool, out, 0);
    epilogue_kernel<<<Nn, 512, EPI_SMEM>>>(emb, mlp_w, mlp_b, out, 1);
}